// round 12
// baseline (speedup 1.0000x reference)
#include <cuda_runtime.h>
#include <cuda_bf16.h>
#include <cstdint>
#include <cstddef>

static constexpr int S = 4096, D = 1024, H = 2048;
static constexpr size_t NSD = (size_t)S * D;
static constexpr size_t NSH = (size_t)S * H;
static constexpr size_t NSS = (size_t)S * S;
static constexpr size_t NDH = (size_t)D * H;

// ===================== helpers (sm_80-era PTX only — compute_100-safe) =====
__device__ __forceinline__ uint32_t tl_smem_u32(const void* p) {
    uint32_t a;
    asm("{ .reg .u64 t; cvta.to.shared.u64 t, %1; cvt.u32.u64 %0, t; }" : "=r"(a) : "l"(p));
    return a;
}

// Row stride inside smem tiles: 128 int8 payload + 16 pad = 144B (conflict-free:
// 16*r mod 128 rotates the 16B bank over 8 rows).
static constexpr int TL_RS = 144;

// ldmatrix x4 for A tile (row-major [M rows][128 int8], 144B row stride).
__device__ __forceinline__ void tl_ldmA(uint32_t base, int am0, int ksb, int lane, uint32_t* a) {
    const uint32_t addr = base +
        (uint32_t)((am0 + (lane & 7) + ((lane >> 3) & 1) * 8) * TL_RS + ksb + (lane >> 4) * 16);
    asm volatile("ldmatrix.sync.aligned.m8n8.x4.shared.b16 {%0,%1,%2,%3}, [%4];"
                 : "=r"(a[0]), "=r"(a[1]), "=r"(a[2]), "=r"(a[3]) : "r"(addr));
}
// ldmatrix x4 for B tile ([N rows][128 int8]): covers n8-tiles nb and nb+8.
__device__ __forceinline__ void tl_ldmB(uint32_t base, int nb, int ksb, int lane, uint32_t* b) {
    const uint32_t addr = base +
        (uint32_t)((nb + (lane & 7) + ((lane >> 4) << 3)) * TL_RS + ksb + ((lane >> 3) & 1) * 16);
    asm volatile("ldmatrix.sync.aligned.m8n8.x4.shared.b16 {%0,%1,%2,%3}, [%4];"
                 : "=r"(b[0]), "=r"(b[1]), "=r"(b[2]), "=r"(b[3]) : "r"(addr));
}
__device__ __forceinline__ void tl_mma_s8(int* c, const uint32_t* a, uint32_t b0, uint32_t b1) {
    asm volatile(
        "mma.sync.aligned.m16n8k32.row.col.s32.s8.s8.s32 "
        "{%0,%1,%2,%3}, {%4,%5,%6,%7}, {%8,%9}, {%0,%1,%2,%3};"
        : "+r"(c[0]), "+r"(c[1]), "+r"(c[2]), "+r"(c[3])
        : "r"(a[0]), "r"(a[1]), "r"(a[2]), "r"(a[3]), "r"(b0), "r"(b1));
}

// Stage layout: A1@0 (18432), A2@18432, B1@36864 (9216), B2@46080. Total 55296.
// A digit tiles: 128 rows x 128 int8 (144B stride). B: 64 rows x 128 int8.
static constexpr int TL_STAGE_B = 55296;
static constexpr int TL_SMEM_TOTAL = 2 * TL_STAGE_B;  // 110592 (x2 CTAs = 221184/SM)

// Fill one stage: 3072 x 16B chunks over 128 threads (24 iters), then commit.
__device__ __forceinline__ void tl_fill(uint32_t smdst,
                                        const int8_t* gA1, const int8_t* gA2,
                                        const int8_t* gB1, const int8_t* gB2,
                                        int lda, int ldb, int tid) {
#pragma unroll
    for (int i = 0; i < 24; i++) {
        const int idx = tid + i * 128;      // 0..3071
        const int8_t* gp;
        uint32_t dst;
        if (idx < 2048) {                   // A: 1024 chunks per digit (128 rows x 8)
            const int tile = idx >> 10, rem = idx & 1023;
            const int r = rem >> 3, ch = rem & 7;
            gp = (tile ? gA2 : gA1) + (size_t)r * lda + ch * 16;
            dst = smdst + (uint32_t)(tile * 18432 + r * TL_RS + ch * 16);
        } else {                            // B: 512 chunks per digit (64 rows x 8)
            const int b = idx - 2048;
            const int tile = b >> 9, rem = b & 511;
            const int r = rem >> 3, ch = rem & 7;
            gp = (tile ? gB2 : gB1) + (size_t)r * ldb + ch * 16;
            dst = smdst + (uint32_t)(36864 + tile * 9216 + r * TL_RS + ch * 16);
        }
        asm volatile("cp.async.cg.shared.global [%0], [%1], 16;" :: "r"(dst), "l"(gp));
    }
    asm volatile("cp.async.commit_group;" ::: "memory");
}

// ===================== scratch ============================================
struct alignas(256) TlScratch {
    int8_t xd1[NSD], xd2[NSD];
    int8_t wq1[NDH], wq2[NDH], wk1[NDH], wk2[NDH], wv1[NDH], wv2[NDH];
    int8_t wo1[NDH], wo2[NDH], w11[NDH], w12[NDH], w21[NDH], w22[NDH];
    float qf[NSH], kf[NSH], vf[NSH];
    int8_t qd1[NSH], qd2[NSH], kd1[NSH], kd2[NSH];
    int8_t vt1[NSH], vt2[NSH];
    int8_t at1[NSS], at2[NSS];
    float aof[NSH];
    int8_t ao1[NSH], ao2[NSH];
    float residf[NSD];
    int8_t rd1[NSD], rd2[NSD];
    float hf[NSH];
    int8_t hd1[NSH], hd2[NSH];
    float scores[NSS];
    float sx[S], sq[S], sk[S], sat[S], sao[S], sr[S], sh[S];
    float swq[H], swk[H], swv[H], sw1[H], svt[H];
    float swo[D], sw2[D];
    unsigned rmk[H], rmv[H], rmvt[H], rm1[H];
    unsigned rmo[D], rm2[D];
};
__device__ TlScratch g_s;

// ===================== int8 GEMM: C = sa*sb*(A1B1 + (A1B2+A2B1)/256) ======
// 128x64 CTA tile, 128 threads (4 warps, warp tile 32x64 -> 4 mma/ldsm),
// K-tile 128, 2-stage cp.async pipeline, 2 CTAs/SM, ~190 regs (256 cap).
// EPI: 0 f32(+bias if nonnull) | 1 f32+bias+addsrc | 2 relu(f32+bias)
// causal: 0 none | 1 skip n0>=m0+128 | 2 clamp K to m0+128
template <int EPI>
__global__ __launch_bounds__(128, 2)
void tl_gemm_i8(const int8_t* __restrict__ A1, const int8_t* __restrict__ A2,
                const float* __restrict__ sa, int lda,
                const int8_t* __restrict__ B1, const int8_t* __restrict__ B2,
                const float* __restrict__ sbv, int ldb,
                int Ktot, int causal,
                float* __restrict__ outf,
                const float* __restrict__ bias, const float* __restrict__ addsrc,
                int out_stride) {
    extern __shared__ char smem[];
    const int tid = threadIdx.x;
    const int lane = tid & 31;
    const int wid = tid >> 5;          // 0..3
    const int m0 = blockIdx.y * 128;
    const int n0 = blockIdx.x * 64;

    if (causal == 1 && n0 >= m0 + 128) return;

    int KT = Ktot >> 7;
    if (causal == 2) {
        const int need = (m0 >> 7) + 1;
        KT = (need < KT) ? need : KT;
    }

    const int wm0 = wid * 32;          // warp covers rows [wm0, wm0+32), all 64 cols
    const uint32_t smb = tl_smem_u32(smem);

    const int8_t* pa1 = A1 + (size_t)m0 * lda;
    const int8_t* pa2 = A2 + (size_t)m0 * lda;
    const int8_t* pb1 = B1 + (size_t)n0 * ldb;
    const int8_t* pb2 = B2 + (size_t)n0 * ldb;

    int acc_hh[2][8][4], acc_x[2][8][4];
#pragma unroll
    for (int mt = 0; mt < 2; mt++)
#pragma unroll
        for (int nt = 0; nt < 8; nt++)
#pragma unroll
            for (int j = 0; j < 4; j++) { acc_hh[mt][nt][j] = 0; acc_x[mt][nt][j] = 0; }

    // 2-stage prologue
    tl_fill(smb, pa1, pa2, pb1, pb2, lda, ldb, tid);

    for (int kt = 0; kt < KT; kt++) {
        if (kt + 1 < KT) {
            const int k1 = (kt + 1) << 7;
            tl_fill(smb + ((kt + 1) & 1) * TL_STAGE_B,
                    pa1 + k1, pa2 + k1, pb1 + k1, pb2 + k1, lda, ldb, tid);
            asm volatile("cp.async.wait_group 1;" ::: "memory");
        } else {
            asm volatile("cp.async.wait_group 0;" ::: "memory");
        }
        __syncthreads();

        const uint32_t st = smb + (kt & 1) * TL_STAGE_B;
        const uint32_t a1b = st, a2b = st + 18432, b1b = st + 36864, b2b = st + 46080;
#pragma unroll
        for (int ks = 0; ks < 4; ks++) {
            const int ksb = ks * 32;
            uint32_t af1[2][4], af2[2][4], bfr[4][4];
            tl_ldmA(a1b, wm0,      ksb, lane, af1[0]);
            tl_ldmA(a1b, wm0 + 16, ksb, lane, af1[1]);
            tl_ldmA(a2b, wm0,      ksb, lane, af2[0]);
            tl_ldmA(a2b, wm0 + 16, ksb, lane, af2[1]);
#pragma unroll
            for (int g = 0; g < 4; g++) tl_ldmB(b1b, g * 16, ksb, lane, bfr[g]);
#pragma unroll
            for (int mt = 0; mt < 2; mt++)
#pragma unroll
                for (int nt = 0; nt < 8; nt++) {
                    const uint32_t b0 = bfr[nt >> 1][(nt & 1) * 2];
                    const uint32_t b1 = bfr[nt >> 1][(nt & 1) * 2 + 1];
                    tl_mma_s8(acc_hh[mt][nt], af1[mt], b0, b1);  // d1*d1
                    tl_mma_s8(acc_x[mt][nt],  af2[mt], b0, b1);  // d2a*d1b
                }
#pragma unroll
            for (int g = 0; g < 4; g++) tl_ldmB(b2b, g * 16, ksb, lane, bfr[g]);
#pragma unroll
            for (int mt = 0; mt < 2; mt++)
#pragma unroll
                for (int nt = 0; nt < 8; nt++)
                    tl_mma_s8(acc_x[mt][nt], af1[mt],            // d1a*d2b
                              bfr[nt >> 1][(nt & 1) * 2], bfr[nt >> 1][(nt & 1) * 2 + 1]);
        }
        __syncthreads();
    }

    // ---- epilogue ----
#pragma unroll
    for (int mt = 0; mt < 2; mt++)
#pragma unroll
        for (int nt = 0; nt < 8; nt++) {
            const int rbase = m0 + wm0 + mt * 16 + (lane >> 2);
            const int cn = n0 + nt * 8 + (lane & 3) * 2;
            const float sb0 = sbv[cn], sb1 = sbv[cn + 1];
#pragma unroll
            for (int h2 = 0; h2 < 2; h2++) {
                const int m = rbase + h2 * 8;
                const float sam = sa[m];
                float v0 = ((float)acc_hh[mt][nt][h2 * 2] +
                            (float)acc_x[mt][nt][h2 * 2] * (1.0f / 256.0f)) * sam * sb0;
                float v1 = ((float)acc_hh[mt][nt][h2 * 2 + 1] +
                            (float)acc_x[mt][nt][h2 * 2 + 1] * (1.0f / 256.0f)) * sam * sb1;
                const size_t ob = (size_t)m * out_stride + cn;
                if (EPI == 0) {
                    if (bias != nullptr) { v0 += bias[cn]; v1 += bias[cn + 1]; }
                } else if (EPI == 1) {
                    v0 += bias[cn] + addsrc[ob];
                    v1 += bias[cn + 1] + addsrc[ob + 1];
                } else {
                    v0 = fmaxf(v0 + bias[cn], 0.f);
                    v1 = fmaxf(v1 + bias[cn + 1], 0.f);
                }
                *(float2*)(outf + ob) = make_float2(v0, v1);
            }
        }
}

// ===================== quantization =======================================
__device__ __forceinline__ void tl_qpair(float y, int8_t& o1, int8_t& o2) {
    const float i1 = rintf(y);
    float i2 = rintf((y - i1) * 256.f);
    i2 = fminf(fmaxf(i2, -127.f), 127.f);
    o1 = (int8_t)(int)i1;
    o2 = (int8_t)(int)i2;
}

// Parallel column abs-max: grid (C/32, R/256), block (32,8); atomicMax on f32 bits.
__global__ void tl_colmax2(const float* __restrict__ in, int C,
                           unsigned* __restrict__ rawmax) {
    const int tx = threadIdx.x, ty = threadIdx.y;
    const int c = blockIdx.x * 32 + tx;
    const int r0 = blockIdx.y * 256;
    __shared__ float red[8][33];
    float m = 0.f;
    for (int r = r0 + ty; r < r0 + 256; r += 8)
        m = fmaxf(m, fabsf(in[(size_t)r * C + c]));
    red[ty][tx] = m;
    __syncthreads();
    if (ty == 0) {
        float M = red[0][tx];
#pragma unroll
        for (int i = 1; i < 8; i++) M = fmaxf(M, red[i][tx]);
        atomicMax(rawmax + c, __float_as_uint(M));
    }
}

// Transpose-quantize [R][C] f32 -> d1,d2 [C][R] using rawmax; writes scale[c]=max/127.
// grid (C/32, R/32), block (32,8)
__global__ void tl_tq(const float* __restrict__ in, const unsigned* __restrict__ rawmax,
                      int R, int C, int8_t* __restrict__ d1, int8_t* __restrict__ d2,
                      float* __restrict__ scale) {
    __shared__ float t[32][33];
    const int c0 = blockIdx.x * 32, r0 = blockIdx.y * 32;
    const int tx = threadIdx.x, ty = threadIdx.y;
#pragma unroll
    for (int i = 0; i < 32; i += 8)
        t[ty + i][tx] = in[(size_t)(r0 + ty + i) * C + c0 + tx];
    if (blockIdx.y == 0 && ty == 0)
        scale[c0 + tx] = __uint_as_float(rawmax[c0 + tx]) * (1.0f / 127.0f);
    __syncthreads();
#pragma unroll
    for (int cc = ty; cc < 32; cc += 8) {
        const float M = __uint_as_float(rawmax[c0 + cc]);
        const float inv = (M > 0.f) ? 127.f / M : 0.f;
        const size_t o = (size_t)(c0 + cc) * R + r0 + tx;
        tl_qpair(t[tx][cc] * inv, d1[o], d2[o]);
    }
}

// Column quantize (single-kernel variant, used for Wq inside prepQ).
__device__ void tl_wquant_body(const float* __restrict__ in, int R, int C,
                               int8_t* __restrict__ d1, int8_t* __restrict__ d2,
                               float* __restrict__ scale, int bx) {
    const int tx = threadIdx.x, ty = threadIdx.y;
    const int c0 = bx * 32;
    __shared__ float red[8][33];
    __shared__ float invs[32];
    __shared__ float t[32][33];
    float m = 0.f;
    for (int r = ty; r < R; r += 8)
        m = fmaxf(m, fabsf(in[(size_t)r * C + c0 + tx]));
    red[ty][tx] = m;
    __syncthreads();
    if (ty == 0) {
        float M = red[0][tx];
#pragma unroll
        for (int i = 1; i < 8; i++) M = fmaxf(M, red[i][tx]);
        invs[tx] = (M > 0.f) ? 127.f / M : 0.f;
        scale[c0 + tx] = M * (1.0f / 127.0f);
    }
    __syncthreads();
    for (int r0 = 0; r0 < R; r0 += 32) {
        for (int i = ty; i < 32; i += 8)
            t[i][tx] = in[(size_t)(r0 + i) * C + c0 + tx];
        __syncthreads();
#pragma unroll
        for (int cc = ty; cc < 32; cc += 8) {
            const float v = t[tx][cc] * invs[cc];
            const size_t o = (size_t)(c0 + cc) * R + r0 + tx;
            tl_qpair(v, d1[o], d2[o]);
        }
        __syncthreads();
    }
}

__global__ void tl_wquant(const float* __restrict__ in, int R, int C,
                          int8_t* __restrict__ d1, int8_t* __restrict__ d2,
                          float* __restrict__ scale) {
    tl_wquant_body(in, R, C, d1, d2, scale, blockIdx.x);
}

// Warp-per-row quantize of [*][ncols] f32 -> d1,d2 + row scale.
__device__ void tl_rowquant_warp(const float* __restrict__ in, int ncols,
                                 int8_t* __restrict__ d1, int8_t* __restrict__ d2,
                                 float* __restrict__ scale, int row) {
    const int tx = threadIdx.x;
    const float* r = in + (size_t)row * ncols;
    float m = 0.f;
    for (int j = tx; j < ncols; j += 32) m = fmaxf(m, fabsf(r[j]));
#pragma unroll
    for (int o = 16; o; o >>= 1) m = fmaxf(m, __shfl_xor_sync(0xffffffffu, m, o));
    const float inv = (m > 0.f) ? 127.f / m : 0.f;
    if (tx == 0) scale[row] = m * (1.0f / 127.0f);
    for (int j = tx; j < ncols; j += 32) {
        const size_t o = (size_t)row * ncols + j;
        tl_qpair(r[j] * inv, d1[o], d2[o]);
    }
}

__global__ void tl_rowquant(const float* __restrict__ in, int ncols,
                            int8_t* __restrict__ d1, int8_t* __restrict__ d2,
                            float* __restrict__ scale) {
    tl_rowquant_warp(in, ncols, d1, d2, scale, blockIdx.x * 8 + (int)threadIdx.y);
}

// Launch #0: Wq quant (blocks 0..63) + x rowquant (64..575) + rawmax zeroing (576).
__global__ void tl_prepQ(const float* __restrict__ Wq, int8_t* wq1, int8_t* wq2, float* swq,
                         const float* __restrict__ x, int8_t* xd1, int8_t* xd2, float* sx,
                         unsigned* rmbase, int rmcount) {
    if (blockIdx.x < 64) {
        tl_wquant_body(Wq, D, H, wq1, wq2, swq, blockIdx.x);
    } else if (blockIdx.x < 576) {
        tl_rowquant_warp(x, D, xd1, xd2, sx, ((int)blockIdx.x - 64) * 8 + (int)threadIdx.y);
    } else {
        const int t = (int)threadIdx.y * 32 + (int)threadIdx.x;
        for (int i = t; i < rmcount; i += 256) rmbase[i] = 0u;
    }
}

// Row-wise causal softmax; writes fp32 attn (zeros above diag) + int8 digits.
__global__ void tl_softmax(const float* __restrict__ scores, float* __restrict__ attn,
                           int8_t* __restrict__ ad1, int8_t* __restrict__ ad2,
                           float* __restrict__ sat) {
    const int row = blockIdx.x;
    const int tid = threadIdx.x;  // 256
    const int nvalid = row + 1;
    const float scale = 0.02209708691207961f;  // 1/sqrt(2048)
    const float* srow = scores + (size_t)row * S;
    __shared__ float red[8];

    float v[16];
    float mx = -1e30f;
#pragma unroll
    for (int t = 0; t < 16; t++) {
        const int j = tid + t * 256;
        const float x = (j < nvalid) ? srow[j] * scale : -1e30f;
        v[t] = x;
        mx = fmaxf(mx, x);
    }
#pragma unroll
    for (int o = 16; o; o >>= 1) mx = fmaxf(mx, __shfl_xor_sync(0xffffffffu, mx, o));
    if ((tid & 31) == 0) red[tid >> 5] = mx;
    __syncthreads();
    float rmax = red[0];
#pragma unroll
    for (int i = 1; i < 8; i++) rmax = fmaxf(rmax, red[i]);
    __syncthreads();

    float sum = 0.f;
#pragma unroll
    for (int t = 0; t < 16; t++) {
        const int j = tid + t * 256;
        const float e = (j < nvalid) ? __expf(v[t] - rmax) : 0.f;
        v[t] = e;
        sum += e;
    }
#pragma unroll
    for (int o = 16; o; o >>= 1) sum += __shfl_xor_sync(0xffffffffu, sum, o);
    if ((tid & 31) == 0) red[tid >> 5] = sum;
    __syncthreads();
    float tot = 0.f;
#pragma unroll
    for (int i = 0; i < 8; i++) tot += red[i];
    const float inv = 1.f / tot;
    if (tid == 0) sat[row] = inv * (1.0f / 127.0f);

#pragma unroll
    for (int t = 0; t < 16; t++) {
        const int j = tid + t * 256;
        const size_t o = (size_t)row * S + j;
        attn[o] = v[t] * inv;
        tl_qpair(v[t] * 127.f, ad1[o], ad2[o]);
    }
}

// ===================== host launch =========================================
extern "C" void kernel_launch(void* const* d_in, const int* in_sizes, int n_in,
                              void* d_out, int out_size) {
    const float* x  = (const float*)d_in[0];
    const float* Wq = (const float*)d_in[1];
    const float* bq = (const float*)d_in[2];
    const float* Wk = (const float*)d_in[3];
    const float* bk = (const float*)d_in[4];
    const float* Wv = (const float*)d_in[5];
    const float* bv = (const float*)d_in[6];
    const float* Wo = (const float*)d_in[7];
    const float* bo = (const float*)d_in[8];
    const float* W1 = (const float*)d_in[9];
    const float* b1 = (const float*)d_in[10];
    const float* W2 = (const float*)d_in[11];
    const float* b2 = (const float*)d_in[12];
    float* out  = (float*)d_out;        // [S,D]
    float* attn = out + NSD;            // [S,S]

    TlScratch* s = nullptr;
    cudaGetSymbolAddress((void**)&s, g_s);

    cudaFuncSetAttribute(tl_gemm_i8<0>, cudaFuncAttributeMaxDynamicSharedMemorySize, TL_SMEM_TOTAL);
    cudaFuncSetAttribute(tl_gemm_i8<1>, cudaFuncAttributeMaxDynamicSharedMemorySize, TL_SMEM_TOTAL);
    cudaFuncSetAttribute(tl_gemm_i8<2>, cudaFuncAttributeMaxDynamicSharedMemorySize, TL_SMEM_TOTAL);

    const dim3 qb(32, 8);
    const dim3 g_sh(H / 64, S / 128);    // [S,H]
    const dim3 g_ss(S / 64, S / 128);    // [S,S]
    const dim3 g_sd(D / 64, S / 128);    // [S,D]

    // rawmax arrays are contiguous in the struct: rmk,rmv,rmvt,rm1 (H each) + rmo,rm2 (D each)
    const int rmcount = 4 * H + 2 * D;

    // #0 prep (Wq quant + x rowquant + rawmax zero); #1 = Q GEMM
    tl_prepQ<<<577, qb>>>(Wq, s->wq1, s->wq2, s->swq, x, s->xd1, s->xd2, s->sx,
                          s->rmk, rmcount);
    tl_gemm_i8<0><<<g_sh, 128, TL_SMEM_TOTAL>>>(s->xd1, s->xd2, s->sx, D,
        s->wq1, s->wq2, s->swq, D, D, 0, s->qf, bq, nullptr, H);
    tl_colmax2<<<dim3(H / 32, D / 256), qb>>>(Wk, H, s->rmk);
    tl_tq<<<dim3(H / 32, D / 32), qb>>>(Wk, s->rmk, D, H, s->wk1, s->wk2, s->swk);
    tl_gemm_i8<0><<<g_sh, 128, TL_SMEM_TOTAL>>>(s->xd1, s->xd2, s->sx, D,
        s->wk1, s->wk2, s->swk, D, D, 0, s->kf, bk, nullptr, H);
    tl_colmax2<<<dim3(H / 32, D / 256), qb>>>(Wv, H, s->rmv);
    tl_tq<<<dim3(H / 32, D / 32), qb>>>(Wv, s->rmv, D, H, s->wv1, s->wv2, s->swv);
    tl_gemm_i8<0><<<g_sh, 128, TL_SMEM_TOTAL>>>(s->xd1, s->xd2, s->sx, D,
        s->wv1, s->wv2, s->swv, D, D, 0, s->vf, bv, nullptr, H);
    tl_rowquant<<<S / 8, qb>>>(s->qf, H, s->qd1, s->qd2, s->sq);
    tl_rowquant<<<S / 8, qb>>>(s->kf, H, s->kd1, s->kd2, s->sk);
    // scores = q@k^T (scale folded into softmax); causal tile skip
    tl_gemm_i8<0><<<g_ss, 128, TL_SMEM_TOTAL>>>(s->qd1, s->qd2, s->sq, H,
        s->kd1, s->kd2, s->sk, H, H, 1, s->scores, nullptr, nullptr, S);
    tl_softmax<<<S, 256>>>(s->scores, attn, s->at1, s->at2, s->sat);
    // v^T quant: parallel colmax + transpose-quantize
    tl_colmax2<<<dim3(H / 32, S / 256), qb>>>(s->vf, H, s->rmvt);
    tl_tq<<<dim3(H / 32, S / 32), qb>>>(s->vf, s->rmvt, S, H, s->vt1, s->vt2, s->svt);
    // attn_out = attn @ v  (K clamped to m0+128)
    tl_gemm_i8<0><<<g_sh, 128, TL_SMEM_TOTAL>>>(s->at1, s->at2, s->sat, S,
        s->vt1, s->vt2, s->svt, S, S, 2, s->aof, nullptr, nullptr, H);
    tl_colmax2<<<dim3(D / 32, H / 256), qb>>>(Wo, D, s->rmo);
    tl_tq<<<dim3(D / 32, H / 32), qb>>>(Wo, s->rmo, H, D, s->wo1, s->wo2, s->swo);
    tl_rowquant<<<S / 8, qb>>>(s->aof, H, s->ao1, s->ao2, s->sao);
    // resid = x + ao@Wo + bo
    tl_gemm_i8<1><<<g_sd, 128, TL_SMEM_TOTAL>>>(s->ao1, s->ao2, s->sao, H,
        s->wo1, s->wo2, s->swo, H, H, 0, s->residf, bo, x, D);
    tl_colmax2<<<dim3(H / 32, D / 256), qb>>>(W1, H, s->rm1);
    tl_tq<<<dim3(H / 32, D / 32), qb>>>(W1, s->rm1, D, H, s->w11, s->w12, s->sw1);
    tl_rowquant<<<S / 8, qb>>>(s->residf, D, s->rd1, s->rd2, s->sr);
    // h = relu(resid@W1 + b1)
    tl_gemm_i8<2><<<g_sh, 128, TL_SMEM_TOTAL>>>(s->rd1, s->rd2, s->sr, D,
        s->w11, s->w12, s->sw1, D, D, 0, s->hf, b1, nullptr, H);
    tl_colmax2<<<dim3(D / 32, H / 256), qb>>>(W2, D, s->rm2);
    tl_tq<<<dim3(D / 32, H / 32), qb>>>(W2, s->rm2, H, D, s->w21, s->w22, s->sw2);
    tl_rowquant<<<S / 8, qb>>>(s->hf, H, s->hd1, s->hd2, s->sh);
    // out = resid + h@W2 + b2
    tl_gemm_i8<1><<<g_sd, 128, TL_SMEM_TOTAL>>>(s->hd1, s->hd2, s->sh, H,
        s->w21, s->w22, s->sw2, H, H, 0, out, b2, s->residf, D);
}

// round 13
// speedup vs baseline: 1.0381x; 1.0381x over previous
#include <cuda_runtime.h>
#include <cuda_bf16.h>
#include <cstdint>
#include <cstddef>

static constexpr int S = 4096, D = 1024, H = 2048;
static constexpr size_t NSD = (size_t)S * D;
static constexpr size_t NSH = (size_t)S * H;
static constexpr size_t NSS = (size_t)S * S;
static constexpr size_t NDH = (size_t)D * H;

// ===================== helpers (sm_80-era PTX only — compute_100-safe) =====
__device__ __forceinline__ uint32_t tl_smem_u32(const void* p) {
    uint32_t a;
    asm("{ .reg .u64 t; cvta.to.shared.u64 t, %1; cvt.u32.u64 %0, t; }" : "=r"(a) : "l"(p));
    return a;
}

// Row stride inside smem tiles: 128 int8 payload + 16 pad = 144B (conflict-free:
// 16*r mod 128 rotates the 16B bank over 8 rows).
static constexpr int TL_RS = 144;

// ldmatrix x4 for A tile (row-major [M rows][128 int8], 144B row stride).
__device__ __forceinline__ void tl_ldmA(uint32_t base, int am0, int ksb, int lane, uint32_t* a) {
    const uint32_t addr = base +
        (uint32_t)((am0 + (lane & 7) + ((lane >> 3) & 1) * 8) * TL_RS + ksb + (lane >> 4) * 16);
    asm volatile("ldmatrix.sync.aligned.m8n8.x4.shared.b16 {%0,%1,%2,%3}, [%4];"
                 : "=r"(a[0]), "=r"(a[1]), "=r"(a[2]), "=r"(a[3]) : "r"(addr));
}
// ldmatrix x4 for B tile ([N rows][128 int8]): covers n8-tiles nb and nb+8.
__device__ __forceinline__ void tl_ldmB(uint32_t base, int nb, int ksb, int lane, uint32_t* b) {
    const uint32_t addr = base +
        (uint32_t)((nb + (lane & 7) + ((lane >> 4) << 3)) * TL_RS + ksb + ((lane >> 3) & 1) * 16);
    asm volatile("ldmatrix.sync.aligned.m8n8.x4.shared.b16 {%0,%1,%2,%3}, [%4];"
                 : "=r"(b[0]), "=r"(b[1]), "=r"(b[2]), "=r"(b[3]) : "r"(addr));
}
__device__ __forceinline__ void tl_mma_s8(int* c, const uint32_t* a, uint32_t b0, uint32_t b1) {
    asm volatile(
        "mma.sync.aligned.m16n8k32.row.col.s32.s8.s8.s32 "
        "{%0,%1,%2,%3}, {%4,%5,%6,%7}, {%8,%9}, {%0,%1,%2,%3};"
        : "+r"(c[0]), "+r"(c[1]), "+r"(c[2]), "+r"(c[3])
        : "r"(a[0]), "r"(a[1]), "r"(a[2]), "r"(a[3]), "r"(b0), "r"(b1));
}

// Load all fragments for one ks step (A hi/lo pair + both B digit tiles).
__device__ __forceinline__ void tl_loadfrags(uint32_t a1b, uint32_t a2b,
                                             uint32_t b1b, uint32_t b2b,
                                             int wm0, int ksb, int lane,
                                             uint32_t af1[2][4], uint32_t af2[2][4],
                                             uint32_t bf1[4][4], uint32_t bf2[4][4]) {
    tl_ldmA(a1b, wm0,      ksb, lane, af1[0]);
    tl_ldmA(a1b, wm0 + 16, ksb, lane, af1[1]);
    tl_ldmA(a2b, wm0,      ksb, lane, af2[0]);
    tl_ldmA(a2b, wm0 + 16, ksb, lane, af2[1]);
#pragma unroll
    for (int g = 0; g < 4; g++) tl_ldmB(b1b, g * 16, ksb, lane, bf1[g]);
#pragma unroll
    for (int g = 0; g < 4; g++) tl_ldmB(b2b, g * 16, ksb, lane, bf2[g]);
}

// Stage layout: A1@0 (18432), A2@18432, B1@36864 (9216), B2@46080. Total 55296.
// A digit tiles: 128 rows x 128 int8 (144B stride). B: 64 rows x 128 int8.
static constexpr int TL_STAGE_B = 55296;
static constexpr int TL_SMEM_TOTAL = 2 * TL_STAGE_B;  // 110592 (x2 CTAs = 221184/SM)

// Fill one stage: 3072 x 16B chunks over 128 threads (24 iters), then commit.
__device__ __forceinline__ void tl_fill(uint32_t smdst,
                                        const int8_t* gA1, const int8_t* gA2,
                                        const int8_t* gB1, const int8_t* gB2,
                                        int lda, int ldb, int tid) {
#pragma unroll
    for (int i = 0; i < 24; i++) {
        const int idx = tid + i * 128;      // 0..3071
        const int8_t* gp;
        uint32_t dst;
        if (idx < 2048) {                   // A: 1024 chunks per digit (128 rows x 8)
            const int tile = idx >> 10, rem = idx & 1023;
            const int r = rem >> 3, ch = rem & 7;
            gp = (tile ? gA2 : gA1) + (size_t)r * lda + ch * 16;
            dst = smdst + (uint32_t)(tile * 18432 + r * TL_RS + ch * 16);
        } else {                            // B: 512 chunks per digit (64 rows x 8)
            const int b = idx - 2048;
            const int tile = b >> 9, rem = b & 511;
            const int r = rem >> 3, ch = rem & 7;
            gp = (tile ? gB2 : gB1) + (size_t)r * ldb + ch * 16;
            dst = smdst + (uint32_t)(36864 + tile * 9216 + r * TL_RS + ch * 16);
        }
        asm volatile("cp.async.cg.shared.global [%0], [%1], 16;" :: "r"(dst), "l"(gp));
    }
    asm volatile("cp.async.commit_group;" ::: "memory");
}

// ===================== scratch ============================================
struct alignas(256) TlScratch {
    int8_t xd1[NSD], xd2[NSD];
    int8_t wq1[NDH], wq2[NDH], wk1[NDH], wk2[NDH], wv1[NDH], wv2[NDH];
    int8_t wo1[NDH], wo2[NDH], w11[NDH], w12[NDH], w21[NDH], w22[NDH];
    float qf[NSH], kf[NSH], vf[NSH];
    int8_t qd1[NSH], qd2[NSH], kd1[NSH], kd2[NSH];
    int8_t vt1[NSH], vt2[NSH];
    int8_t at1[NSS], at2[NSS];
    float aof[NSH];
    int8_t ao1[NSH], ao2[NSH];
    float residf[NSD];
    int8_t rd1[NSD], rd2[NSD];
    float hf[NSH];
    int8_t hd1[NSH], hd2[NSH];
    float scores[NSS];
    float sx[S], sq[S], sk[S], sat[S], sao[S], sr[S], sh[S];
    float swq[H], swk[H], swv[H], sw1[H], svt[H];
    float swo[D], sw2[D];
    unsigned rmk[H], rmv[H], rmvt[H], rm1[H];
    unsigned rmo[D], rm2[D];
};
__device__ TlScratch g_s;

// ===================== int8 GEMM: C = sa*sb*(A1B1 + (A1B2+A2B1)/256) ======
// 128x64 CTA tile, 128 threads (4 warps, warp tile 32x64), K-tile 128,
// 2-stage cp.async gmem pipeline + ks-level fragment double buffering,
// 2 CTAs/SM. Heavy-first m ordering (reversed blockIdx.y).
// EPI: 0 f32(+bias if nonnull) | 1 f32+bias+addsrc | 2 relu(f32+bias)
// causal: 0 none | 1 skip n0>=m0+128 | 2 clamp K to m0+128
template <int EPI>
__global__ __launch_bounds__(128, 2)
void tl_gemm_i8(const int8_t* __restrict__ A1, const int8_t* __restrict__ A2,
                const float* __restrict__ sa, int lda,
                const int8_t* __restrict__ B1, const int8_t* __restrict__ B2,
                const float* __restrict__ sbv, int ldb,
                int Ktot, int causal,
                float* __restrict__ outf,
                const float* __restrict__ bias, const float* __restrict__ addsrc,
                int out_stride) {
    extern __shared__ char smem[];
    const int tid = threadIdx.x;
    const int lane = tid & 31;
    const int wid = tid >> 5;          // 0..3
    const int m0 = ((int)gridDim.y - 1 - (int)blockIdx.y) * 128;  // heavy-first
    const int n0 = blockIdx.x * 64;

    if (causal == 1 && n0 >= m0 + 128) return;

    int KT = Ktot >> 7;
    if (causal == 2) {
        const int need = (m0 >> 7) + 1;
        KT = (need < KT) ? need : KT;
    }

    const int wm0 = wid * 32;          // warp covers rows [wm0, wm0+32), all 64 cols
    const uint32_t smb = tl_smem_u32(smem);

    const int8_t* pa1 = A1 + (size_t)m0 * lda;
    const int8_t* pa2 = A2 + (size_t)m0 * lda;
    const int8_t* pb1 = B1 + (size_t)n0 * ldb;
    const int8_t* pb2 = B2 + (size_t)n0 * ldb;

    int acc_hh[2][8][4], acc_x[2][8][4];
#pragma unroll
    for (int mt = 0; mt < 2; mt++)
#pragma unroll
        for (int nt = 0; nt < 8; nt++)
#pragma unroll
            for (int j = 0; j < 4; j++) { acc_hh[mt][nt][j] = 0; acc_x[mt][nt][j] = 0; }

    // 2-stage gmem prologue
    tl_fill(smb, pa1, pa2, pb1, pb2, lda, ldb, tid);

    for (int kt = 0; kt < KT; kt++) {
        if (kt + 1 < KT) {
            const int k1 = (kt + 1) << 7;
            tl_fill(smb + ((kt + 1) & 1) * TL_STAGE_B,
                    pa1 + k1, pa2 + k1, pb1 + k1, pb2 + k1, lda, ldb, tid);
            asm volatile("cp.async.wait_group 1;" ::: "memory");
        } else {
            asm volatile("cp.async.wait_group 0;" ::: "memory");
        }
        __syncthreads();

        const uint32_t st = smb + (kt & 1) * TL_STAGE_B;
        const uint32_t a1b = st, a2b = st + 18432, b1b = st + 36864, b2b = st + 46080;

        // ks-level fragment double buffering: load ks+1 while mma'ing ks.
        uint32_t af1[2][2][4], af2[2][2][4], bf1[2][4][4], bf2[2][4][4];
        tl_loadfrags(a1b, a2b, b1b, b2b, wm0, 0, lane,
                     af1[0], af2[0], bf1[0], bf2[0]);
#pragma unroll
        for (int ks = 0; ks < 4; ks++) {
            const int cur = ks & 1, nxt = cur ^ 1;
            if (ks < 3)
                tl_loadfrags(a1b, a2b, b1b, b2b, wm0, (ks + 1) * 32, lane,
                             af1[nxt], af2[nxt], bf1[nxt], bf2[nxt]);
#pragma unroll
            for (int mt = 0; mt < 2; mt++)
#pragma unroll
                for (int nt = 0; nt < 8; nt++) {
                    const uint32_t b0 = bf1[cur][nt >> 1][(nt & 1) * 2];
                    const uint32_t b1 = bf1[cur][nt >> 1][(nt & 1) * 2 + 1];
                    tl_mma_s8(acc_hh[mt][nt], af1[cur][mt], b0, b1);  // d1*d1
                    tl_mma_s8(acc_x[mt][nt],  af2[cur][mt], b0, b1);  // d2a*d1b
                }
#pragma unroll
            for (int mt = 0; mt < 2; mt++)
#pragma unroll
                for (int nt = 0; nt < 8; nt++)
                    tl_mma_s8(acc_x[mt][nt], af1[cur][mt],            // d1a*d2b
                              bf2[cur][nt >> 1][(nt & 1) * 2],
                              bf2[cur][nt >> 1][(nt & 1) * 2 + 1]);
        }
        __syncthreads();
    }

    // ---- epilogue ----
#pragma unroll
    for (int mt = 0; mt < 2; mt++)
#pragma unroll
        for (int nt = 0; nt < 8; nt++) {
            const int rbase = m0 + wm0 + mt * 16 + (lane >> 2);
            const int cn = n0 + nt * 8 + (lane & 3) * 2;
            const float sb0 = sbv[cn], sb1 = sbv[cn + 1];
#pragma unroll
            for (int h2 = 0; h2 < 2; h2++) {
                const int m = rbase + h2 * 8;
                const float sam = sa[m];
                float v0 = ((float)acc_hh[mt][nt][h2 * 2] +
                            (float)acc_x[mt][nt][h2 * 2] * (1.0f / 256.0f)) * sam * sb0;
                float v1 = ((float)acc_hh[mt][nt][h2 * 2 + 1] +
                            (float)acc_x[mt][nt][h2 * 2 + 1] * (1.0f / 256.0f)) * sam * sb1;
                const size_t ob = (size_t)m * out_stride + cn;
                if (EPI == 0) {
                    if (bias != nullptr) { v0 += bias[cn]; v1 += bias[cn + 1]; }
                } else if (EPI == 1) {
                    v0 += bias[cn] + addsrc[ob];
                    v1 += bias[cn + 1] + addsrc[ob + 1];
                } else {
                    v0 = fmaxf(v0 + bias[cn], 0.f);
                    v1 = fmaxf(v1 + bias[cn + 1], 0.f);
                }
                *(float2*)(outf + ob) = make_float2(v0, v1);
            }
        }
}

// ===================== quantization =======================================
__device__ __forceinline__ void tl_qpair(float y, int8_t& o1, int8_t& o2) {
    const float i1 = rintf(y);
    float i2 = rintf((y - i1) * 256.f);
    i2 = fminf(fmaxf(i2, -127.f), 127.f);
    o1 = (int8_t)(int)i1;
    o2 = (int8_t)(int)i2;
}

// Parallel column abs-max: grid (C/32, R/256), block (32,8); atomicMax on f32 bits.
__global__ void tl_colmax2(const float* __restrict__ in, int C,
                           unsigned* __restrict__ rawmax) {
    const int tx = threadIdx.x, ty = threadIdx.y;
    const int c = blockIdx.x * 32 + tx;
    const int r0 = blockIdx.y * 256;
    __shared__ float red[8][33];
    float m = 0.f;
    for (int r = r0 + ty; r < r0 + 256; r += 8)
        m = fmaxf(m, fabsf(in[(size_t)r * C + c]));
    red[ty][tx] = m;
    __syncthreads();
    if (ty == 0) {
        float M = red[0][tx];
#pragma unroll
        for (int i = 1; i < 8; i++) M = fmaxf(M, red[i][tx]);
        atomicMax(rawmax + c, __float_as_uint(M));
    }
}

// Transpose-quantize [R][C] f32 -> d1,d2 [C][R] using rawmax; writes scale[c]=max/127.
// grid (C/32, R/32), block (32,8)
__global__ void tl_tq(const float* __restrict__ in, const unsigned* __restrict__ rawmax,
                      int R, int C, int8_t* __restrict__ d1, int8_t* __restrict__ d2,
                      float* __restrict__ scale) {
    __shared__ float t[32][33];
    const int c0 = blockIdx.x * 32, r0 = blockIdx.y * 32;
    const int tx = threadIdx.x, ty = threadIdx.y;
#pragma unroll
    for (int i = 0; i < 32; i += 8)
        t[ty + i][tx] = in[(size_t)(r0 + ty + i) * C + c0 + tx];
    if (blockIdx.y == 0 && ty == 0)
        scale[c0 + tx] = __uint_as_float(rawmax[c0 + tx]) * (1.0f / 127.0f);
    __syncthreads();
#pragma unroll
    for (int cc = ty; cc < 32; cc += 8) {
        const float M = __uint_as_float(rawmax[c0 + cc]);
        const float inv = (M > 0.f) ? 127.f / M : 0.f;
        const size_t o = (size_t)(c0 + cc) * R + r0 + tx;
        tl_qpair(t[tx][cc] * inv, d1[o], d2[o]);
    }
}

// Column quantize (single-kernel variant, used for Wq inside prepQ).
__device__ void tl_wquant_body(const float* __restrict__ in, int R, int C,
                               int8_t* __restrict__ d1, int8_t* __restrict__ d2,
                               float* __restrict__ scale, int bx) {
    const int tx = threadIdx.x, ty = threadIdx.y;
    const int c0 = bx * 32;
    __shared__ float red[8][33];
    __shared__ float invs[32];
    __shared__ float t[32][33];
    float m = 0.f;
    for (int r = ty; r < R; r += 8)
        m = fmaxf(m, fabsf(in[(size_t)r * C + c0 + tx]));
    red[ty][tx] = m;
    __syncthreads();
    if (ty == 0) {
        float M = red[0][tx];
#pragma unroll
        for (int i = 1; i < 8; i++) M = fmaxf(M, red[i][tx]);
        invs[tx] = (M > 0.f) ? 127.f / M : 0.f;
        scale[c0 + tx] = M * (1.0f / 127.0f);
    }
    __syncthreads();
    for (int r0 = 0; r0 < R; r0 += 32) {
        for (int i = ty; i < 32; i += 8)
            t[i][tx] = in[(size_t)(r0 + i) * C + c0 + tx];
        __syncthreads();
#pragma unroll
        for (int cc = ty; cc < 32; cc += 8) {
            const float v = t[tx][cc] * invs[cc];
            const size_t o = (size_t)(c0 + cc) * R + r0 + tx;
            tl_qpair(v, d1[o], d2[o]);
        }
        __syncthreads();
    }
}

// Warp-per-row quantize (float4 vectorized) of [*][ncols] f32 -> d1,d2 + scale.
__device__ void tl_rowquant_warp(const float* __restrict__ in, int ncols,
                                 int8_t* __restrict__ d1, int8_t* __restrict__ d2,
                                 float* __restrict__ scale, int row) {
    const int tx = threadIdx.x;
    const float* r = in + (size_t)row * ncols;
    float m = 0.f;
    for (int j = tx * 4; j < ncols; j += 128) {
        const float4 v = *(const float4*)(r + j);
        m = fmaxf(m, fmaxf(fmaxf(fabsf(v.x), fabsf(v.y)), fmaxf(fabsf(v.z), fabsf(v.w))));
    }
#pragma unroll
    for (int o = 16; o; o >>= 1) m = fmaxf(m, __shfl_xor_sync(0xffffffffu, m, o));
    const float inv = (m > 0.f) ? 127.f / m : 0.f;
    if (tx == 0) scale[row] = m * (1.0f / 127.0f);
    for (int j = tx * 4; j < ncols; j += 128) {
        const float4 v = *(const float4*)(r + j);
        int8_t a1, a2, b1, b2, c1, c2, e1, e2;
        tl_qpair(v.x * inv, a1, a2);
        tl_qpair(v.y * inv, b1, b2);
        tl_qpair(v.z * inv, c1, c2);
        tl_qpair(v.w * inv, e1, e2);
        const uint32_t p1 = (uint32_t)(uint8_t)a1 | ((uint32_t)(uint8_t)b1 << 8) |
                            ((uint32_t)(uint8_t)c1 << 16) | ((uint32_t)(uint8_t)e1 << 24);
        const uint32_t p2 = (uint32_t)(uint8_t)a2 | ((uint32_t)(uint8_t)b2 << 8) |
                            ((uint32_t)(uint8_t)c2 << 16) | ((uint32_t)(uint8_t)e2 << 24);
        const size_t o = (size_t)row * ncols + j;
        *(uint32_t*)(d1 + o) = p1;
        *(uint32_t*)(d2 + o) = p2;
    }
}

__global__ void tl_rowquant(const float* __restrict__ in, int ncols,
                            int8_t* __restrict__ d1, int8_t* __restrict__ d2,
                            float* __restrict__ scale) {
    tl_rowquant_warp(in, ncols, d1, d2, scale, blockIdx.x * 8 + (int)threadIdx.y);
}

// Launch #0: Wq quant (blocks 0..63) + x rowquant (64..575) + rawmax zeroing (576).
__global__ void tl_prepQ(const float* __restrict__ Wq, int8_t* wq1, int8_t* wq2, float* swq,
                         const float* __restrict__ x, int8_t* xd1, int8_t* xd2, float* sx,
                         unsigned* rmbase, int rmcount) {
    if (blockIdx.x < 64) {
        tl_wquant_body(Wq, D, H, wq1, wq2, swq, blockIdx.x);
    } else if (blockIdx.x < 576) {
        tl_rowquant_warp(x, D, xd1, xd2, sx, ((int)blockIdx.x - 64) * 8 + (int)threadIdx.y);
    } else {
        const int t = (int)threadIdx.y * 32 + (int)threadIdx.x;
        for (int i = t; i < rmcount; i += 256) rmbase[i] = 0u;
    }
}

// Row-wise causal softmax; writes fp32 attn (zeros above diag) + int8 digits.
__global__ void tl_softmax(const float* __restrict__ scores, float* __restrict__ attn,
                           int8_t* __restrict__ ad1, int8_t* __restrict__ ad2,
                           float* __restrict__ sat) {
    const int row = blockIdx.x;
    const int tid = threadIdx.x;  // 256
    const int nvalid = row + 1;
    const float scale = 0.02209708691207961f;  // 1/sqrt(2048)
    const float* srow = scores + (size_t)row * S;
    __shared__ float red[8];

    float v[16];
    float mx = -1e30f;
#pragma unroll
    for (int t = 0; t < 16; t++) {
        const int j = tid + t * 256;
        const float x = (j < nvalid) ? srow[j] * scale : -1e30f;
        v[t] = x;
        mx = fmaxf(mx, x);
    }
#pragma unroll
    for (int o = 16; o; o >>= 1) mx = fmaxf(mx, __shfl_xor_sync(0xffffffffu, mx, o));
    if ((tid & 31) == 0) red[tid >> 5] = mx;
    __syncthreads();
    float rmax = red[0];
#pragma unroll
    for (int i = 1; i < 8; i++) rmax = fmaxf(rmax, red[i]);
    __syncthreads();

    float sum = 0.f;
#pragma unroll
    for (int t = 0; t < 16; t++) {
        const int j = tid + t * 256;
        const float e = (j < nvalid) ? __expf(v[t] - rmax) : 0.f;
        v[t] = e;
        sum += e;
    }
#pragma unroll
    for (int o = 16; o; o >>= 1) sum += __shfl_xor_sync(0xffffffffu, sum, o);
    if ((tid & 31) == 0) red[tid >> 5] = sum;
    __syncthreads();
    float tot = 0.f;
#pragma unroll
    for (int i = 0; i < 8; i++) tot += red[i];
    const float inv = 1.f / tot;
    if (tid == 0) sat[row] = inv * (1.0f / 127.0f);

#pragma unroll
    for (int t = 0; t < 16; t++) {
        const int j = tid + t * 256;
        const size_t o = (size_t)row * S + j;
        attn[o] = v[t] * inv;
        tl_qpair(v[t] * 127.f, ad1[o], ad2[o]);
    }
}

// ===================== host launch =========================================
extern "C" void kernel_launch(void* const* d_in, const int* in_sizes, int n_in,
                              void* d_out, int out_size) {
    const float* x  = (const float*)d_in[0];
    const float* Wq = (const float*)d_in[1];
    const float* bq = (const float*)d_in[2];
    const float* Wk = (const float*)d_in[3];
    const float* bk = (const float*)d_in[4];
    const float* Wv = (const float*)d_in[5];
    const float* bv = (const float*)d_in[6];
    const float* Wo = (const float*)d_in[7];
    const float* bo = (const float*)d_in[8];
    const float* W1 = (const float*)d_in[9];
    const float* b1 = (const float*)d_in[10];
    const float* W2 = (const float*)d_in[11];
    const float* b2 = (const float*)d_in[12];
    float* out  = (float*)d_out;        // [S,D]
    float* attn = out + NSD;            // [S,S]

    TlScratch* s = nullptr;
    cudaGetSymbolAddress((void**)&s, g_s);

    cudaFuncSetAttribute(tl_gemm_i8<0>, cudaFuncAttributeMaxDynamicSharedMemorySize, TL_SMEM_TOTAL);
    cudaFuncSetAttribute(tl_gemm_i8<1>, cudaFuncAttributeMaxDynamicSharedMemorySize, TL_SMEM_TOTAL);
    cudaFuncSetAttribute(tl_gemm_i8<2>, cudaFuncAttributeMaxDynamicSharedMemorySize, TL_SMEM_TOTAL);

    const dim3 qb(32, 8);
    const dim3 g_sh(H / 64, S / 128);    // [S,H]
    const dim3 g_ss(S / 64, S / 128);    // [S,S]
    const dim3 g_sd(D / 64, S / 128);    // [S,D]

    // rawmax arrays are contiguous in the struct: rmk,rmv,rmvt,rm1 (H each) + rmo,rm2 (D each)
    const int rmcount = 4 * H + 2 * D;

    // #0 prep (Wq quant + x rowquant + rawmax zero); #1 = Q GEMM
    tl_prepQ<<<577, qb>>>(Wq, s->wq1, s->wq2, s->swq, x, s->xd1, s->xd2, s->sx,
                          s->rmk, rmcount);
    tl_gemm_i8<0><<<g_sh, 128, TL_SMEM_TOTAL>>>(s->xd1, s->xd2, s->sx, D,
        s->wq1, s->wq2, s->swq, D, D, 0, s->qf, bq, nullptr, H);
    tl_colmax2<<<dim3(H / 32, D / 256), qb>>>(Wk, H, s->rmk);
    tl_tq<<<dim3(H / 32, D / 32), qb>>>(Wk, s->rmk, D, H, s->wk1, s->wk2, s->swk);
    tl_gemm_i8<0><<<g_sh, 128, TL_SMEM_TOTAL>>>(s->xd1, s->xd2, s->sx, D,
        s->wk1, s->wk2, s->swk, D, D, 0, s->kf, bk, nullptr, H);
    tl_colmax2<<<dim3(H / 32, D / 256), qb>>>(Wv, H, s->rmv);
    tl_tq<<<dim3(H / 32, D / 32), qb>>>(Wv, s->rmv, D, H, s->wv1, s->wv2, s->swv);
    tl_gemm_i8<0><<<g_sh, 128, TL_SMEM_TOTAL>>>(s->xd1, s->xd2, s->sx, D,
        s->wv1, s->wv2, s->swv, D, D, 0, s->vf, bv, nullptr, H);
    tl_rowquant<<<S / 8, qb>>>(s->qf, H, s->qd1, s->qd2, s->sq);
    tl_rowquant<<<S / 8, qb>>>(s->kf, H, s->kd1, s->kd2, s->sk);
    // scores = q@k^T (scale folded into softmax); causal tile skip
    tl_gemm_i8<0><<<g_ss, 128, TL_SMEM_TOTAL>>>(s->qd1, s->qd2, s->sq, H,
        s->kd1, s->kd2, s->sk, H, H, 1, s->scores, nullptr, nullptr, S);
    tl_softmax<<<S, 256>>>(s->scores, attn, s->at1, s->at2, s->sat);
    // v^T quant: parallel colmax + transpose-quantize
    tl_colmax2<<<dim3(H / 32, S / 256), qb>>>(s->vf, H, s->rmvt);
    tl_tq<<<dim3(H / 32, S / 32), qb>>>(s->vf, s->rmvt, S, H, s->vt1, s->vt2, s->svt);
    // attn_out = attn @ v  (K clamped to m0+128)
    tl_gemm_i8<0><<<g_sh, 128, TL_SMEM_TOTAL>>>(s->at1, s->at2, s->sat, S,
        s->vt1, s->vt2, s->svt, S, S, 2, s->aof, nullptr, nullptr, H);
    tl_colmax2<<<dim3(D / 32, H / 256), qb>>>(Wo, D, s->rmo);
    tl_tq<<<dim3(D / 32, H / 32), qb>>>(Wo, s->rmo, H, D, s->wo1, s->wo2, s->swo);
    tl_rowquant<<<S / 8, qb>>>(s->aof, H, s->ao1, s->ao2, s->sao);
    // resid = x + ao@Wo + bo
    tl_gemm_i8<1><<<g_sd, 128, TL_SMEM_TOTAL>>>(s->ao1, s->ao2, s->sao, H,
        s->wo1, s->wo2, s->swo, H, H, 0, s->residf, bo, x, D);
    tl_colmax2<<<dim3(H / 32, D / 256), qb>>>(W1, H, s->rm1);
    tl_tq<<<dim3(H / 32, D / 32), qb>>>(W1, s->rm1, D, H, s->w11, s->w12, s->sw1);
    tl_rowquant<<<S / 8, qb>>>(s->residf, D, s->rd1, s->rd2, s->sr);
    // h = relu(resid@W1 + b1)
    tl_gemm_i8<2><<<g_sh, 128, TL_SMEM_TOTAL>>>(s->rd1, s->rd2, s->sr, D,
        s->w11, s->w12, s->sw1, D, D, 0, s->hf, b1, nullptr, H);
    tl_colmax2<<<dim3(D / 32, H / 256), qb>>>(W2, D, s->rm2);
    tl_tq<<<dim3(D / 32, H / 32), qb>>>(W2, s->rm2, H, D, s->w21, s->w22, s->sw2);
    tl_rowquant<<<S / 8, qb>>>(s->hf, H, s->hd1, s->hd2, s->sh);
    // out = resid + h@W2 + b2
    tl_gemm_i8<1><<<g_sd, 128, TL_SMEM_TOTAL>>>(s->hd1, s->hd2, s->sh, H,
        s->w21, s->w22, s->sw2, H, H, 0, out, b2, s->residf, D);
}

// round 14
// speedup vs baseline: 1.0531x; 1.0145x over previous
#include <cuda_runtime.h>
#include <cuda_bf16.h>
#include <cstdint>
#include <cstddef>

static constexpr int S = 4096, D = 1024, H = 2048;
static constexpr size_t NSD = (size_t)S * D;
static constexpr size_t NSH = (size_t)S * H;
static constexpr size_t NSS = (size_t)S * S;
static constexpr size_t NDH = (size_t)D * H;

// ===================== helpers (sm_80-era PTX only — compute_100-safe) =====
__device__ __forceinline__ uint32_t tl_smem_u32(const void* p) {
    uint32_t a;
    asm("{ .reg .u64 t; cvta.to.shared.u64 t, %1; cvt.u32.u64 %0, t; }" : "=r"(a) : "l"(p));
    return a;
}

// Row stride inside smem tiles: 128 int8 payload + 16 pad = 144B (conflict-free).
static constexpr int TL_RS = 144;

// ldmatrix x4 for A tile (row-major [M rows][128 int8], 144B row stride).
__device__ __forceinline__ void tl_ldmA(uint32_t base, int am0, int ksb, int lane, uint32_t* a) {
    const uint32_t addr = base +
        (uint32_t)((am0 + (lane & 7) + ((lane >> 3) & 1) * 8) * TL_RS + ksb + (lane >> 4) * 16);
    asm volatile("ldmatrix.sync.aligned.m8n8.x4.shared.b16 {%0,%1,%2,%3}, [%4];"
                 : "=r"(a[0]), "=r"(a[1]), "=r"(a[2]), "=r"(a[3]) : "r"(addr));
}
// ldmatrix x4 for B tile ([N rows][128 int8]): covers n8-tiles nb and nb+8.
__device__ __forceinline__ void tl_ldmB(uint32_t base, int nb, int ksb, int lane, uint32_t* b) {
    const uint32_t addr = base +
        (uint32_t)((nb + (lane & 7) + ((lane >> 4) << 3)) * TL_RS + ksb + ((lane >> 3) & 1) * 16);
    asm volatile("ldmatrix.sync.aligned.m8n8.x4.shared.b16 {%0,%1,%2,%3}, [%4];"
                 : "=r"(b[0]), "=r"(b[1]), "=r"(b[2]), "=r"(b[3]) : "r"(addr));
}
__device__ __forceinline__ void tl_mma_s8(int* c, const uint32_t* a, uint32_t b0, uint32_t b1) {
    asm volatile(
        "mma.sync.aligned.m16n8k32.row.col.s32.s8.s8.s32 "
        "{%0,%1,%2,%3}, {%4,%5,%6,%7}, {%8,%9}, {%0,%1,%2,%3};"
        : "+r"(c[0]), "+r"(c[1]), "+r"(c[2]), "+r"(c[3])
        : "r"(a[0]), "r"(a[1]), "r"(a[2]), "r"(a[3]), "r"(b0), "r"(b1));
}

// Load all fragments for one ks step (A hi/lo pair + both B digit tiles).
__device__ __forceinline__ void tl_loadfrags(uint32_t a1b, uint32_t a2b,
                                             uint32_t b1b, uint32_t b2b,
                                             int wm0, int ksb, int lane,
                                             uint32_t af1[2][4], uint32_t af2[2][4],
                                             uint32_t bf1[4][4], uint32_t bf2[4][4]) {
    tl_ldmA(a1b, wm0,      ksb, lane, af1[0]);
    tl_ldmA(a1b, wm0 + 16, ksb, lane, af1[1]);
    tl_ldmA(a2b, wm0,      ksb, lane, af2[0]);
    tl_ldmA(a2b, wm0 + 16, ksb, lane, af2[1]);
#pragma unroll
    for (int g = 0; g < 4; g++) tl_ldmB(b1b, g * 16, ksb, lane, bf1[g]);
#pragma unroll
    for (int g = 0; g < 4; g++) tl_ldmB(b2b, g * 16, ksb, lane, bf2[g]);
}

// Stage layout: A1@0 (18432), A2@18432, B1@36864 (9216), B2@46080. Total 55296.
static constexpr int TL_STAGE_B = 55296;
static constexpr int TL_SMEM_TOTAL = 2 * TL_STAGE_B;  // 110592 (x2 CTAs/SM)

// Fill one stage: 3072 x 16B chunks over 128 threads (24 iters), then commit.
__device__ __forceinline__ void tl_fill(uint32_t smdst,
                                        const int8_t* gA1, const int8_t* gA2,
                                        const int8_t* gB1, const int8_t* gB2,
                                        int lda, int ldb, int tid) {
#pragma unroll
    for (int i = 0; i < 24; i++) {
        const int idx = tid + i * 128;      // 0..3071
        const int8_t* gp;
        uint32_t dst;
        if (idx < 2048) {                   // A: 1024 chunks per digit
            const int tile = idx >> 10, rem = idx & 1023;
            const int r = rem >> 3, ch = rem & 7;
            gp = (tile ? gA2 : gA1) + (size_t)r * lda + ch * 16;
            dst = smdst + (uint32_t)(tile * 18432 + r * TL_RS + ch * 16);
        } else {                            // B: 512 chunks per digit
            const int b = idx - 2048;
            const int tile = b >> 9, rem = b & 511;
            const int r = rem >> 3, ch = rem & 7;
            gp = (tile ? gB2 : gB1) + (size_t)r * ldb + ch * 16;
            dst = smdst + (uint32_t)(36864 + tile * 9216 + r * TL_RS + ch * 16);
        }
        asm volatile("cp.async.cg.shared.global [%0], [%1], 16;" :: "r"(dst), "l"(gp));
    }
    asm volatile("cp.async.commit_group;" ::: "memory");
}

// ===================== scratch ============================================
struct alignas(256) TlScratch {
    int8_t xd1[NSD], xd2[NSD];
    int8_t wq1[NDH], wq2[NDH], wk1[NDH], wk2[NDH], wv1[NDH], wv2[NDH];
    int8_t wo1[NDH], wo2[NDH], w11[NDH], w12[NDH], w21[NDH], w22[NDH];
    float qf[NSH], kf[NSH], vf[NSH];
    int8_t qd1[NSH], qd2[NSH], kd1[NSH], kd2[NSH];
    int8_t vt1[NSH], vt2[NSH];
    int8_t at1[NSS], at2[NSS];
    float aof[NSH];
    int8_t ao1[NSH], ao2[NSH];
    float residf[NSD];
    int8_t rd1[NSD], rd2[NSD];
    float hf[NSH];
    int8_t hd1[NSH], hd2[NSH];
    float scores[NSS];
    float sx[S], sq[S], sk[S], sat[S], sao[S], sr[S], sh[S];
    float swq[H], swk[H], swv[H], sw1[H], svt[H];
    float swo[D], sw2[D];
    // rawmax arrays (contiguous block, zeroed in prepQ): 2H + 2D + 5S words
    unsigned rmvt[H], rm1[H];
    unsigned rmo[D], rm2[D];
    unsigned rmq[S], rmkf[S], rmao[S], rmres[S], rmh[S];
};
__device__ TlScratch g_s;

// ===================== int8 GEMM: C = sa*sb*(A1B1 + (A1B2+A2B1)/256) ======
// 128x64 CTA tile, 128 threads (4 warps, warp tile 32x64), K-tile 128,
// 2-stage cp.async gmem pipeline + ks fragment double buffering, 2 CTAs/SM,
// heavy-first m ordering.
// EPI low 2 bits: 0 f32(+bias if nonnull) | 1 f32+bias+addsrc | 2 relu(f32+bias)
// EPI bit 2 (|4): row abs-max -> atomicMax(rmrow). bit 3 (|8): col abs-max -> rmcol.
// causal: 0 none | 1 skip n0>=m0+128 | 2 clamp K to m0+128
template <int EPI>
__global__ __launch_bounds__(128, 2)
void tl_gemm_i8(const int8_t* __restrict__ A1, const int8_t* __restrict__ A2,
                const float* __restrict__ sa, int lda,
                const int8_t* __restrict__ B1, const int8_t* __restrict__ B2,
                const float* __restrict__ sbv, int ldb,
                int Ktot, int causal,
                float* __restrict__ outf,
                const float* __restrict__ bias, const float* __restrict__ addsrc,
                int out_stride,
                unsigned* __restrict__ rmrow, unsigned* __restrict__ rmcol) {
    extern __shared__ char smem[];
    const int tid = threadIdx.x;
    const int lane = tid & 31;
    const int wid = tid >> 5;
    const int m0 = ((int)gridDim.y - 1 - (int)blockIdx.y) * 128;  // heavy-first
    const int n0 = blockIdx.x * 64;

    if (causal == 1 && n0 >= m0 + 128) return;

    int KT = Ktot >> 7;
    if (causal == 2) {
        const int need = (m0 >> 7) + 1;
        KT = (need < KT) ? need : KT;
    }

    const int wm0 = wid * 32;
    const uint32_t smb = tl_smem_u32(smem);

    const int8_t* pa1 = A1 + (size_t)m0 * lda;
    const int8_t* pa2 = A2 + (size_t)m0 * lda;
    const int8_t* pb1 = B1 + (size_t)n0 * ldb;
    const int8_t* pb2 = B2 + (size_t)n0 * ldb;

    int acc_hh[2][8][4], acc_x[2][8][4];
#pragma unroll
    for (int mt = 0; mt < 2; mt++)
#pragma unroll
        for (int nt = 0; nt < 8; nt++)
#pragma unroll
            for (int j = 0; j < 4; j++) { acc_hh[mt][nt][j] = 0; acc_x[mt][nt][j] = 0; }

    tl_fill(smb, pa1, pa2, pb1, pb2, lda, ldb, tid);

    for (int kt = 0; kt < KT; kt++) {
        if (kt + 1 < KT) {
            const int k1 = (kt + 1) << 7;
            tl_fill(smb + ((kt + 1) & 1) * TL_STAGE_B,
                    pa1 + k1, pa2 + k1, pb1 + k1, pb2 + k1, lda, ldb, tid);
            asm volatile("cp.async.wait_group 1;" ::: "memory");
        } else {
            asm volatile("cp.async.wait_group 0;" ::: "memory");
        }
        __syncthreads();

        const uint32_t st = smb + (kt & 1) * TL_STAGE_B;
        const uint32_t a1b = st, a2b = st + 18432, b1b = st + 36864, b2b = st + 46080;

        uint32_t af1[2][2][4], af2[2][2][4], bf1[2][4][4], bf2[2][4][4];
        tl_loadfrags(a1b, a2b, b1b, b2b, wm0, 0, lane,
                     af1[0], af2[0], bf1[0], bf2[0]);
#pragma unroll
        for (int ks = 0; ks < 4; ks++) {
            const int cur = ks & 1, nxt = cur ^ 1;
            if (ks < 3)
                tl_loadfrags(a1b, a2b, b1b, b2b, wm0, (ks + 1) * 32, lane,
                             af1[nxt], af2[nxt], bf1[nxt], bf2[nxt]);
#pragma unroll
            for (int mt = 0; mt < 2; mt++)
#pragma unroll
                for (int nt = 0; nt < 8; nt++) {
                    const uint32_t b0 = bf1[cur][nt >> 1][(nt & 1) * 2];
                    const uint32_t b1 = bf1[cur][nt >> 1][(nt & 1) * 2 + 1];
                    tl_mma_s8(acc_hh[mt][nt], af1[cur][mt], b0, b1);
                    tl_mma_s8(acc_x[mt][nt],  af2[cur][mt], b0, b1);
                }
#pragma unroll
            for (int mt = 0; mt < 2; mt++)
#pragma unroll
                for (int nt = 0; nt < 8; nt++)
                    tl_mma_s8(acc_x[mt][nt], af1[cur][mt],
                              bf2[cur][nt >> 1][(nt & 1) * 2],
                              bf2[cur][nt >> 1][(nt & 1) * 2 + 1]);
        }
        __syncthreads();
    }

    // ---- epilogue (with optional fused row/col abs-max) ----
    float rowm[2][2] = {{0.f, 0.f}, {0.f, 0.f}};
    float colm[8][2];
    if (EPI & 8) {
#pragma unroll
        for (int nt = 0; nt < 8; nt++) { colm[nt][0] = 0.f; colm[nt][1] = 0.f; }
    }
#pragma unroll
    for (int mt = 0; mt < 2; mt++)
#pragma unroll
        for (int nt = 0; nt < 8; nt++) {
            const int rbase = m0 + wm0 + mt * 16 + (lane >> 2);
            const int cn = n0 + nt * 8 + (lane & 3) * 2;
            const float sb0 = sbv[cn], sb1 = sbv[cn + 1];
#pragma unroll
            for (int h2 = 0; h2 < 2; h2++) {
                const int m = rbase + h2 * 8;
                const float sam = sa[m];
                float v0 = ((float)acc_hh[mt][nt][h2 * 2] +
                            (float)acc_x[mt][nt][h2 * 2] * (1.0f / 256.0f)) * sam * sb0;
                float v1 = ((float)acc_hh[mt][nt][h2 * 2 + 1] +
                            (float)acc_x[mt][nt][h2 * 2 + 1] * (1.0f / 256.0f)) * sam * sb1;
                const size_t ob = (size_t)m * out_stride + cn;
                const int base = EPI & 3;
                if (base == 0) {
                    if (bias != nullptr) { v0 += bias[cn]; v1 += bias[cn + 1]; }
                } else if (base == 1) {
                    v0 += bias[cn] + addsrc[ob];
                    v1 += bias[cn + 1] + addsrc[ob + 1];
                } else {
                    v0 = fmaxf(v0 + bias[cn], 0.f);
                    v1 = fmaxf(v1 + bias[cn + 1], 0.f);
                }
                *(float2*)(outf + ob) = make_float2(v0, v1);
                if (EPI & 4)
                    rowm[mt][h2] = fmaxf(rowm[mt][h2], fmaxf(fabsf(v0), fabsf(v1)));
                if (EPI & 8) {
                    colm[nt][0] = fmaxf(colm[nt][0], fabsf(v0));
                    colm[nt][1] = fmaxf(colm[nt][1], fabsf(v1));
                }
            }
        }
    if (EPI & 4) {
#pragma unroll
        for (int mt = 0; mt < 2; mt++)
#pragma unroll
            for (int h2 = 0; h2 < 2; h2++) {
                const int m = m0 + wm0 + mt * 16 + (lane >> 2) + h2 * 8;
                atomicMax(rmrow + m, __float_as_uint(rowm[mt][h2]));
            }
    }
    if (EPI & 8) {
#pragma unroll
        for (int nt = 0; nt < 8; nt++) {
            const int cn = n0 + nt * 8 + (lane & 3) * 2;
            atomicMax(rmcol + cn, __float_as_uint(colm[nt][0]));
            atomicMax(rmcol + cn + 1, __float_as_uint(colm[nt][1]));
        }
    }
}

// ===================== quantization =======================================
__device__ __forceinline__ void tl_qpair(float y, int8_t& o1, int8_t& o2) {
    const float i1 = rintf(y);
    float i2 = rintf((y - i1) * 256.f);
    i2 = fminf(fmaxf(i2, -127.f), 127.f);
    o1 = (int8_t)(int)i1;
    o2 = (int8_t)(int)i2;
}

// Parallel column abs-max: grid (C/32, R/256), block (32,8); atomicMax on f32 bits.
__global__ void tl_colmax2(const float* __restrict__ in, int C,
                           unsigned* __restrict__ rawmax) {
    const int tx = threadIdx.x, ty = threadIdx.y;
    const int c = blockIdx.x * 32 + tx;
    const int r0 = blockIdx.y * 256;
    __shared__ float red[8][33];
    float m = 0.f;
    for (int r = r0 + ty; r < r0 + 256; r += 8)
        m = fmaxf(m, fabsf(in[(size_t)r * C + c]));
    red[ty][tx] = m;
    __syncthreads();
    if (ty == 0) {
        float M = red[0][tx];
#pragma unroll
        for (int i = 1; i < 8; i++) M = fmaxf(M, red[i][tx]);
        atomicMax(rawmax + c, __float_as_uint(M));
    }
}

// Transpose-quantize [R][C] f32 -> d1,d2 [C][R] using rawmax; writes scale[c]=max/127.
__global__ void tl_tq(const float* __restrict__ in, const unsigned* __restrict__ rawmax,
                      int R, int C, int8_t* __restrict__ d1, int8_t* __restrict__ d2,
                      float* __restrict__ scale) {
    __shared__ float t[32][33];
    const int c0 = blockIdx.x * 32, r0 = blockIdx.y * 32;
    const int tx = threadIdx.x, ty = threadIdx.y;
#pragma unroll
    for (int i = 0; i < 32; i += 8)
        t[ty + i][tx] = in[(size_t)(r0 + ty + i) * C + c0 + tx];
    if (blockIdx.y == 0 && ty == 0)
        scale[c0 + tx] = __uint_as_float(rawmax[c0 + tx]) * (1.0f / 127.0f);
    __syncthreads();
#pragma unroll
    for (int cc = ty; cc < 32; cc += 8) {
        const float M = __uint_as_float(rawmax[c0 + cc]);
        const float inv = (M > 0.f) ? 127.f / M : 0.f;
        const size_t o = (size_t)(c0 + cc) * R + r0 + tx;
        tl_qpair(t[tx][cc] * inv, d1[o], d2[o]);
    }
}

// Column quantize (two-pass within one block; used for weights inside prepQ).
__device__ void tl_wquant_body(const float* __restrict__ in, int R, int C,
                               int8_t* __restrict__ d1, int8_t* __restrict__ d2,
                               float* __restrict__ scale, int bx) {
    const int tx = threadIdx.x, ty = threadIdx.y;
    const int c0 = bx * 32;
    __shared__ float red[8][33];
    __shared__ float invs[32];
    __shared__ float t[32][33];
    float m = 0.f;
    for (int r = ty; r < R; r += 8)
        m = fmaxf(m, fabsf(in[(size_t)r * C + c0 + tx]));
    red[ty][tx] = m;
    __syncthreads();
    if (ty == 0) {
        float M = red[0][tx];
#pragma unroll
        for (int i = 1; i < 8; i++) M = fmaxf(M, red[i][tx]);
        invs[tx] = (M > 0.f) ? 127.f / M : 0.f;
        scale[c0 + tx] = M * (1.0f / 127.0f);
    }
    __syncthreads();
    for (int r0 = 0; r0 < R; r0 += 32) {
        for (int i = ty; i < 32; i += 8)
            t[i][tx] = in[(size_t)(r0 + i) * C + c0 + tx];
        __syncthreads();
#pragma unroll
        for (int cc = ty; cc < 32; cc += 8) {
            const float v = t[tx][cc] * invs[cc];
            const size_t o = (size_t)(c0 + cc) * R + r0 + tx;
            tl_qpair(v, d1[o], d2[o]);
        }
        __syncthreads();
    }
}

// Warp-per-row quantize (own max; float4 vectorized) — used for x in prepQ.
__device__ void tl_rowquant_warp(const float* __restrict__ in, int ncols,
                                 int8_t* __restrict__ d1, int8_t* __restrict__ d2,
                                 float* __restrict__ scale, int row) {
    const int tx = threadIdx.x;
    const float* r = in + (size_t)row * ncols;
    float m = 0.f;
    for (int j = tx * 4; j < ncols; j += 128) {
        const float4 v = *(const float4*)(r + j);
        m = fmaxf(m, fmaxf(fmaxf(fabsf(v.x), fabsf(v.y)), fmaxf(fabsf(v.z), fabsf(v.w))));
    }
#pragma unroll
    for (int o = 16; o; o >>= 1) m = fmaxf(m, __shfl_xor_sync(0xffffffffu, m, o));
    const float inv = (m > 0.f) ? 127.f / m : 0.f;
    if (tx == 0) scale[row] = m * (1.0f / 127.0f);
    for (int j = tx * 4; j < ncols; j += 128) {
        const float4 v = *(const float4*)(r + j);
        int8_t a1, a2, b1, b2, c1, c2, e1, e2;
        tl_qpair(v.x * inv, a1, a2);
        tl_qpair(v.y * inv, b1, b2);
        tl_qpair(v.z * inv, c1, c2);
        tl_qpair(v.w * inv, e1, e2);
        const uint32_t p1 = (uint32_t)(uint8_t)a1 | ((uint32_t)(uint8_t)b1 << 8) |
                            ((uint32_t)(uint8_t)c1 << 16) | ((uint32_t)(uint8_t)e1 << 24);
        const uint32_t p2 = (uint32_t)(uint8_t)a2 | ((uint32_t)(uint8_t)b2 << 8) |
                            ((uint32_t)(uint8_t)c2 << 16) | ((uint32_t)(uint8_t)e2 << 24);
        const size_t o = (size_t)row * ncols + j;
        *(uint32_t*)(d1 + o) = p1;
        *(uint32_t*)(d2 + o) = p2;
    }
}

// Row quantize with PRECOMPUTED row max (from fused GEMM epilogue) — single read.
__global__ void tl_rowquant2(const float* __restrict__ in, int ncols,
                             const unsigned* __restrict__ rmax,
                             int8_t* __restrict__ d1, int8_t* __restrict__ d2,
                             float* __restrict__ scale) {
    const int row = blockIdx.x * 8 + (int)threadIdx.y;
    const int tx = threadIdx.x;
    const float M = __uint_as_float(rmax[row]);
    const float inv = (M > 0.f) ? 127.f / M : 0.f;
    if (tx == 0) scale[row] = M * (1.0f / 127.0f);
    const float* r = in + (size_t)row * ncols;
    for (int j = tx * 4; j < ncols; j += 128) {
        const float4 v = *(const float4*)(r + j);
        int8_t a1, a2, b1, b2, c1, c2, e1, e2;
        tl_qpair(v.x * inv, a1, a2);
        tl_qpair(v.y * inv, b1, b2);
        tl_qpair(v.z * inv, c1, c2);
        tl_qpair(v.w * inv, e1, e2);
        const uint32_t p1 = (uint32_t)(uint8_t)a1 | ((uint32_t)(uint8_t)b1 << 8) |
                            ((uint32_t)(uint8_t)c1 << 16) | ((uint32_t)(uint8_t)e1 << 24);
        const uint32_t p2 = (uint32_t)(uint8_t)a2 | ((uint32_t)(uint8_t)b2 << 8) |
                            ((uint32_t)(uint8_t)c2 << 16) | ((uint32_t)(uint8_t)e2 << 24);
        const size_t o = (size_t)row * ncols + j;
        *(uint32_t*)(d1 + o) = p1;
        *(uint32_t*)(d2 + o) = p2;
    }
}

// Launch #0: Wq/Wk/Wv quant (blocks 0..191) + x rowquant (192..703) + rawmax zero (704).
__global__ void tl_prepQ(const float* __restrict__ Wq, int8_t* wq1, int8_t* wq2, float* swq,
                         const float* __restrict__ Wk, int8_t* wk1, int8_t* wk2, float* swk,
                         const float* __restrict__ Wv, int8_t* wv1, int8_t* wv2, float* swv,
                         const float* __restrict__ x, int8_t* xd1, int8_t* xd2, float* sx,
                         unsigned* rmbase, int rmcount) {
    const int b = blockIdx.x;
    if (b < 64) {
        tl_wquant_body(Wq, D, H, wq1, wq2, swq, b);
    } else if (b < 128) {
        tl_wquant_body(Wk, D, H, wk1, wk2, swk, b - 64);
    } else if (b < 192) {
        tl_wquant_body(Wv, D, H, wv1, wv2, swv, b - 128);
    } else if (b < 704) {
        tl_rowquant_warp(x, D, xd1, xd2, sx, (b - 192) * 8 + (int)threadIdx.y);
    } else {
        const int t = (int)threadIdx.y * 32 + (int)threadIdx.x;
        for (int i = t; i < rmcount; i += 256) rmbase[i] = 0u;
    }
}

// Row-wise causal softmax; writes fp32 attn (zeros above diag) + int8 digits.
__global__ void tl_softmax(const float* __restrict__ scores, float* __restrict__ attn,
                           int8_t* __restrict__ ad1, int8_t* __restrict__ ad2,
                           float* __restrict__ sat) {
    const int row = blockIdx.x;
    const int tid = threadIdx.x;  // 256
    const int nvalid = row + 1;
    const float scale = 0.02209708691207961f;  // 1/sqrt(2048)
    const float* srow = scores + (size_t)row * S;
    __shared__ float red[8];

    float v[16];
    float mx = -1e30f;
#pragma unroll
    for (int t = 0; t < 16; t++) {
        const int j = tid + t * 256;
        const float x = (j < nvalid) ? srow[j] * scale : -1e30f;
        v[t] = x;
        mx = fmaxf(mx, x);
    }
#pragma unroll
    for (int o = 16; o; o >>= 1) mx = fmaxf(mx, __shfl_xor_sync(0xffffffffu, mx, o));
    if ((tid & 31) == 0) red[tid >> 5] = mx;
    __syncthreads();
    float rmax = red[0];
#pragma unroll
    for (int i = 1; i < 8; i++) rmax = fmaxf(rmax, red[i]);
    __syncthreads();

    float sum = 0.f;
#pragma unroll
    for (int t = 0; t < 16; t++) {
        const int j = tid + t * 256;
        const float e = (j < nvalid) ? __expf(v[t] - rmax) : 0.f;
        v[t] = e;
        sum += e;
    }
#pragma unroll
    for (int o = 16; o; o >>= 1) sum += __shfl_xor_sync(0xffffffffu, sum, o);
    if ((tid & 31) == 0) red[tid >> 5] = sum;
    __syncthreads();
    float tot = 0.f;
#pragma unroll
    for (int i = 0; i < 8; i++) tot += red[i];
    const float inv = 1.f / tot;
    if (tid == 0) sat[row] = inv * (1.0f / 127.0f);

#pragma unroll
    for (int t = 0; t < 16; t++) {
        const int j = tid + t * 256;
        const size_t o = (size_t)row * S + j;
        attn[o] = v[t] * inv;
        tl_qpair(v[t] * 127.f, ad1[o], ad2[o]);
    }
}

// ===================== host launch =========================================
extern "C" void kernel_launch(void* const* d_in, const int* in_sizes, int n_in,
                              void* d_out, int out_size) {
    const float* x  = (const float*)d_in[0];
    const float* Wq = (const float*)d_in[1];
    const float* bq = (const float*)d_in[2];
    const float* Wk = (const float*)d_in[3];
    const float* bk = (const float*)d_in[4];
    const float* Wv = (const float*)d_in[5];
    const float* bv = (const float*)d_in[6];
    const float* Wo = (const float*)d_in[7];
    const float* bo = (const float*)d_in[8];
    const float* W1 = (const float*)d_in[9];
    const float* b1 = (const float*)d_in[10];
    const float* W2 = (const float*)d_in[11];
    const float* b2 = (const float*)d_in[12];
    float* out  = (float*)d_out;        // [S,D]
    float* attn = out + NSD;            // [S,S]

    TlScratch* s = nullptr;
    cudaGetSymbolAddress((void**)&s, g_s);

    cudaFuncSetAttribute(tl_gemm_i8<0>, cudaFuncAttributeMaxDynamicSharedMemorySize, TL_SMEM_TOTAL);
    cudaFuncSetAttribute(tl_gemm_i8<1>, cudaFuncAttributeMaxDynamicSharedMemorySize, TL_SMEM_TOTAL);
    cudaFuncSetAttribute(tl_gemm_i8<4>, cudaFuncAttributeMaxDynamicSharedMemorySize, TL_SMEM_TOTAL);
    cudaFuncSetAttribute(tl_gemm_i8<5>, cudaFuncAttributeMaxDynamicSharedMemorySize, TL_SMEM_TOTAL);
    cudaFuncSetAttribute(tl_gemm_i8<6>, cudaFuncAttributeMaxDynamicSharedMemorySize, TL_SMEM_TOTAL);
    cudaFuncSetAttribute(tl_gemm_i8<8>, cudaFuncAttributeMaxDynamicSharedMemorySize, TL_SMEM_TOTAL);

    const dim3 qb(32, 8);
    const dim3 g_sh(H / 64, S / 128);    // [S,H]
    const dim3 g_ss(S / 64, S / 128);    // [S,S]
    const dim3 g_sd(D / 64, S / 128);    // [S,D]

    // rawmax block: rmvt,rm1 (H) + rmo,rm2 (D) + rmq,rmkf,rmao,rmres,rmh (S each)
    const int rmcount = 2 * H + 2 * D + 5 * S;

    // #0 prep (Wq/Wk/Wv quant + x rowquant + rawmax zero); #1..#3 = Q/K/V GEMMs
    tl_prepQ<<<705, qb>>>(Wq, s->wq1, s->wq2, s->swq,
                          Wk, s->wk1, s->wk2, s->swk,
                          Wv, s->wv1, s->wv2, s->swv,
                          x, s->xd1, s->xd2, s->sx, s->rmvt, rmcount);
    tl_gemm_i8<4><<<g_sh, 128, TL_SMEM_TOTAL>>>(s->xd1, s->xd2, s->sx, D,
        s->wq1, s->wq2, s->swq, D, D, 0, s->qf, bq, nullptr, H, s->rmq, nullptr);
    tl_gemm_i8<4><<<g_sh, 128, TL_SMEM_TOTAL>>>(s->xd1, s->xd2, s->sx, D,
        s->wk1, s->wk2, s->swk, D, D, 0, s->kf, bk, nullptr, H, s->rmkf, nullptr);
    tl_gemm_i8<8><<<g_sh, 128, TL_SMEM_TOTAL>>>(s->xd1, s->xd2, s->sx, D,
        s->wv1, s->wv2, s->swv, D, D, 0, s->vf, bv, nullptr, H, nullptr, s->rmvt);
    tl_rowquant2<<<S / 8, qb>>>(s->qf, H, s->rmq, s->qd1, s->qd2, s->sq);
    tl_rowquant2<<<S / 8, qb>>>(s->kf, H, s->rmkf, s->kd1, s->kd2, s->sk);
    // scores = q@k^T (scale folded into softmax); causal tile skip
    tl_gemm_i8<0><<<g_ss, 128, TL_SMEM_TOTAL>>>(s->qd1, s->qd2, s->sq, H,
        s->kd1, s->kd2, s->sk, H, H, 1, s->scores, nullptr, nullptr, S, nullptr, nullptr);
    tl_softmax<<<S, 256>>>(s->scores, attn, s->at1, s->at2, s->sat);
    // v^T quant: colmax fused in V-GEMM epilogue; only transpose-quantize here
    tl_tq<<<dim3(H / 32, S / 32), qb>>>(s->vf, s->rmvt, S, H, s->vt1, s->vt2, s->svt);
    // attn_out = attn @ v  (K clamped to m0+128); fused row-max
    tl_gemm_i8<4><<<g_sh, 128, TL_SMEM_TOTAL>>>(s->at1, s->at2, s->sat, S,
        s->vt1, s->vt2, s->svt, S, S, 2, s->aof, nullptr, nullptr, H, s->rmao, nullptr);
    tl_colmax2<<<dim3(D / 32, H / 256), qb>>>(Wo, D, s->rmo);
    tl_tq<<<dim3(D / 32, H / 32), qb>>>(Wo, s->rmo, H, D, s->wo1, s->wo2, s->swo);
    tl_rowquant2<<<S / 8, qb>>>(s->aof, H, s->rmao, s->ao1, s->ao2, s->sao);
    // resid = x + ao@Wo + bo (fused row-max)
    tl_gemm_i8<5><<<g_sd, 128, TL_SMEM_TOTAL>>>(s->ao1, s->ao2, s->sao, H,
        s->wo1, s->wo2, s->swo, H, H, 0, s->residf, bo, x, D, s->rmres, nullptr);
    tl_colmax2<<<dim3(H / 32, D / 256), qb>>>(W1, H, s->rm1);
    tl_tq<<<dim3(H / 32, D / 32), qb>>>(W1, s->rm1, D, H, s->w11, s->w12, s->sw1);
    tl_rowquant2<<<S / 8, qb>>>(s->residf, D, s->rmres, s->rd1, s->rd2, s->sr);
    // h = relu(resid@W1 + b1) (fused row-max)
    tl_gemm_i8<6><<<g_sh, 128, TL_SMEM_TOTAL>>>(s->rd1, s->rd2, s->sr, D,
        s->w11, s->w12, s->sw1, D, D, 0, s->hf, b1, nullptr, H, s->rmh, nullptr);
    tl_colmax2<<<dim3(D / 32, H / 256), qb>>>(W2, D, s->rm2);
    tl_tq<<<dim3(D / 32, H / 32), qb>>>(W2, s->rm2, H, D, s->w21, s->w22, s->sw2);
    tl_rowquant2<<<S / 8, qb>>>(s->hf, H, s->rmh, s->hd1, s->hd2, s->sh);
    // out = resid + h@W2 + b2
    tl_gemm_i8<1><<<g_sd, 128, TL_SMEM_TOTAL>>>(s->hd1, s->hd2, s->sh, H,
        s->w21, s->w22, s->sw2, H, H, 0, out, b2, s->residf, D, nullptr, nullptr);
}

// round 16
// speedup vs baseline: 1.0893x; 1.0344x over previous
#include <cuda_runtime.h>
#include <cuda_bf16.h>
#include <cstdint>
#include <cstddef>

static constexpr int S = 4096, D = 1024, H = 2048;
static constexpr size_t NSD = (size_t)S * D;
static constexpr size_t NSH = (size_t)S * H;
static constexpr size_t NSS = (size_t)S * S;
static constexpr size_t NDH = (size_t)D * H;

// ===================== helpers (sm_80-era PTX only — compute_100-safe) =====
__device__ __forceinline__ uint32_t tl_smem_u32(const void* p) {
    uint32_t a;
    asm("{ .reg .u64 t; cvta.to.shared.u64 t, %1; cvt.u32.u64 %0, t; }" : "=r"(a) : "l"(p));
    return a;
}

// Row stride inside smem tiles: 128 int8 payload + 16 pad = 144B (conflict-free).
static constexpr int TL_RS = 144;

// ldmatrix x4 for A tile (row-major [M rows][128 int8], 144B row stride).
__device__ __forceinline__ void tl_ldmA(uint32_t base, int am0, int ksb, int lane, uint32_t* a) {
    const uint32_t addr = base +
        (uint32_t)((am0 + (lane & 7) + ((lane >> 3) & 1) * 8) * TL_RS + ksb + (lane >> 4) * 16);
    asm volatile("ldmatrix.sync.aligned.m8n8.x4.shared.b16 {%0,%1,%2,%3}, [%4];"
                 : "=r"(a[0]), "=r"(a[1]), "=r"(a[2]), "=r"(a[3]) : "r"(addr));
}
// ldmatrix x4 for B tile ([N rows][128 int8]): covers n8-tiles nb and nb+8.
__device__ __forceinline__ void tl_ldmB(uint32_t base, int nb, int ksb, int lane, uint32_t* b) {
    const uint32_t addr = base +
        (uint32_t)((nb + (lane & 7) + ((lane >> 4) << 3)) * TL_RS + ksb + ((lane >> 3) & 1) * 16);
    asm volatile("ldmatrix.sync.aligned.m8n8.x4.shared.b16 {%0,%1,%2,%3}, [%4];"
                 : "=r"(b[0]), "=r"(b[1]), "=r"(b[2]), "=r"(b[3]) : "r"(addr));
}
__device__ __forceinline__ void tl_mma_s8(int* c, const uint32_t* a, uint32_t b0, uint32_t b1) {
    asm volatile(
        "mma.sync.aligned.m16n8k32.row.col.s32.s8.s8.s32 "
        "{%0,%1,%2,%3}, {%4,%5,%6,%7}, {%8,%9}, {%0,%1,%2,%3};"
        : "+r"(c[0]), "+r"(c[1]), "+r"(c[2]), "+r"(c[3])
        : "r"(a[0]), "r"(a[1]), "r"(a[2]), "r"(a[3]), "r"(b0), "r"(b1));
}

// Load all fragments for one ks step (A hi/lo pair + both B digit tiles).
__device__ __forceinline__ void tl_loadfrags(uint32_t a1b, uint32_t a2b,
                                             uint32_t b1b, uint32_t b2b,
                                             int wm0, int ksb, int lane,
                                             uint32_t af1[2][4], uint32_t af2[2][4],
                                             uint32_t bf1[4][4], uint32_t bf2[4][4]) {
    tl_ldmA(a1b, wm0,      ksb, lane, af1[0]);
    tl_ldmA(a1b, wm0 + 16, ksb, lane, af1[1]);
    tl_ldmA(a2b, wm0,      ksb, lane, af2[0]);
    tl_ldmA(a2b, wm0 + 16, ksb, lane, af2[1]);
#pragma unroll
    for (int g = 0; g < 4; g++) tl_ldmB(b1b, g * 16, ksb, lane, bf1[g]);
#pragma unroll
    for (int g = 0; g < 4; g++) tl_ldmB(b2b, g * 16, ksb, lane, bf2[g]);
}

// Stage layout: A1@0 (18432), A2@18432, B1@36864 (9216), B2@46080. Total 55296.
static constexpr int TL_STAGE_B = 55296;
static constexpr int TL_SMEM_TOTAL = 2 * TL_STAGE_B;  // 110592 (x2 CTAs/SM)

// Fill one stage: 3072 x 16B chunks over 128 threads (24 iters), then commit.
__device__ __forceinline__ void tl_fill(uint32_t smdst,
                                        const int8_t* gA1, const int8_t* gA2,
                                        const int8_t* gB1, const int8_t* gB2,
                                        int lda, int ldb, int tid) {
#pragma unroll
    for (int i = 0; i < 24; i++) {
        const int idx = tid + i * 128;      // 0..3071
        const int8_t* gp;
        uint32_t dst;
        if (idx < 2048) {                   // A: 1024 chunks per digit
            const int tile = idx >> 10, rem = idx & 1023;
            const int r = rem >> 3, ch = rem & 7;
            gp = (tile ? gA2 : gA1) + (size_t)r * lda + ch * 16;
            dst = smdst + (uint32_t)(tile * 18432 + r * TL_RS + ch * 16);
        } else {                            // B: 512 chunks per digit
            const int b = idx - 2048;
            const int tile = b >> 9, rem = b & 511;
            const int r = rem >> 3, ch = rem & 7;
            gp = (tile ? gB2 : gB1) + (size_t)r * ldb + ch * 16;
            dst = smdst + (uint32_t)(36864 + tile * 9216 + r * TL_RS + ch * 16);
        }
        asm volatile("cp.async.cg.shared.global [%0], [%1], 16;" :: "r"(dst), "l"(gp));
    }
    asm volatile("cp.async.commit_group;" ::: "memory");
}

// ===================== scratch ============================================
struct alignas(256) TlScratch {
    int8_t xd1[NSD], xd2[NSD];
    int8_t wq1[NDH], wq2[NDH], wk1[NDH], wk2[NDH], wv1[NDH], wv2[NDH];
    int8_t wo1[NDH], wo2[NDH], w11[NDH], w12[NDH], w21[NDH], w22[NDH];
    float qf[NSH], kf[NSH], vf[NSH];
    int8_t qd1[NSH], qd2[NSH], kd1[NSH], kd2[NSH];
    int8_t vt1[NSH], vt2[NSH];
    int8_t at1[NSS], at2[NSS];
    float aof[NSH];
    int8_t ao1[NSH], ao2[NSH];
    float residf[NSD];
    int8_t rd1[NSD], rd2[NSD];
    float hf[NSH];
    int8_t hd1[NSH], hd2[NSH];
    float scores[NSS];
    float sx[S], sq[S], sk[S], sat[S], sao[S], sr[S], sh[S];
    float swq[H], swk[H], swv[H], sw1[H], svt[H];
    float swo[D], sw2[D];
    // rawmax arrays (contiguous block, zeroed in prepQ): 2H + 2D + 5S words
    unsigned rmvt[H], rm1[H];
    unsigned rmo[D], rm2[D];
    unsigned rmq[S], rmkf[S], rmao[S], rmres[S], rmh[S];
};
__device__ TlScratch g_s;

// ===================== int8 GEMM: C = sa*sb*(A1B1 + (A1B2+A2B1)/256) ======
// 128x64 CTA tile, 128 threads (4 warps, warp tile 32x64), K-tile 128,
// 2-stage cp.async gmem pipeline + ks fragment double buffering, 2 CTAs/SM,
// heavy-first m ordering.
// EPI low 2 bits: 0 f32(+bias if nonnull) | 1 f32+bias+addsrc | 2 relu(f32+bias)
// EPI bit 2 (|4): row abs-max -> atomicMax(rmrow). bit 3 (|8): col abs-max -> rmcol.
// causal: 0 none | 1 skip n0>=m0+128 | 2 clamp K to m0+128
template <int EPI>
__global__ __launch_bounds__(128, 2)
void tl_gemm_i8(const int8_t* __restrict__ A1, const int8_t* __restrict__ A2,
                const float* __restrict__ sa, int lda,
                const int8_t* __restrict__ B1, const int8_t* __restrict__ B2,
                const float* __restrict__ sbv, int ldb,
                int Ktot, int causal,
                float* __restrict__ outf,
                const float* __restrict__ bias, const float* __restrict__ addsrc,
                int out_stride,
                unsigned* __restrict__ rmrow, unsigned* __restrict__ rmcol) {
    extern __shared__ char smem[];
    const int tid = threadIdx.x;
    const int lane = tid & 31;
    const int wid = tid >> 5;
    const int m0 = ((int)gridDim.y - 1 - (int)blockIdx.y) * 128;  // heavy-first
    const int n0 = blockIdx.x * 64;

    if (causal == 1 && n0 >= m0 + 128) return;

    int KT = Ktot >> 7;
    if (causal == 2) {
        const int need = (m0 >> 7) + 1;
        KT = (need < KT) ? need : KT;
    }

    const int wm0 = wid * 32;
    const uint32_t smb = tl_smem_u32(smem);

    const int8_t* pa1 = A1 + (size_t)m0 * lda;
    const int8_t* pa2 = A2 + (size_t)m0 * lda;
    const int8_t* pb1 = B1 + (size_t)n0 * ldb;
    const int8_t* pb2 = B2 + (size_t)n0 * ldb;

    int acc_hh[2][8][4], acc_x[2][8][4];
#pragma unroll
    for (int mt = 0; mt < 2; mt++)
#pragma unroll
        for (int nt = 0; nt < 8; nt++)
#pragma unroll
            for (int j = 0; j < 4; j++) { acc_hh[mt][nt][j] = 0; acc_x[mt][nt][j] = 0; }

    tl_fill(smb, pa1, pa2, pb1, pb2, lda, ldb, tid);

    for (int kt = 0; kt < KT; kt++) {
        if (kt + 1 < KT) {
            const int k1 = (kt + 1) << 7;
            tl_fill(smb + ((kt + 1) & 1) * TL_STAGE_B,
                    pa1 + k1, pa2 + k1, pb1 + k1, pb2 + k1, lda, ldb, tid);
            asm volatile("cp.async.wait_group 1;" ::: "memory");
        } else {
            asm volatile("cp.async.wait_group 0;" ::: "memory");
        }
        __syncthreads();

        const uint32_t st = smb + (kt & 1) * TL_STAGE_B;
        const uint32_t a1b = st, a2b = st + 18432, b1b = st + 36864, b2b = st + 46080;

        uint32_t af1[2][2][4], af2[2][2][4], bf1[2][4][4], bf2[2][4][4];
        tl_loadfrags(a1b, a2b, b1b, b2b, wm0, 0, lane,
                     af1[0], af2[0], bf1[0], bf2[0]);
#pragma unroll
        for (int ks = 0; ks < 4; ks++) {
            const int cur = ks & 1, nxt = cur ^ 1;
            if (ks < 3)
                tl_loadfrags(a1b, a2b, b1b, b2b, wm0, (ks + 1) * 32, lane,
                             af1[nxt], af2[nxt], bf1[nxt], bf2[nxt]);
#pragma unroll
            for (int mt = 0; mt < 2; mt++)
#pragma unroll
                for (int nt = 0; nt < 8; nt++) {
                    const uint32_t b0 = bf1[cur][nt >> 1][(nt & 1) * 2];
                    const uint32_t b1 = bf1[cur][nt >> 1][(nt & 1) * 2 + 1];
                    tl_mma_s8(acc_hh[mt][nt], af1[cur][mt], b0, b1);
                    tl_mma_s8(acc_x[mt][nt],  af2[cur][mt], b0, b1);
                }
#pragma unroll
            for (int mt = 0; mt < 2; mt++)
#pragma unroll
                for (int nt = 0; nt < 8; nt++)
                    tl_mma_s8(acc_x[mt][nt], af1[cur][mt],
                              bf2[cur][nt >> 1][(nt & 1) * 2],
                              bf2[cur][nt >> 1][(nt & 1) * 2 + 1]);
        }
        __syncthreads();
    }

    // ---- epilogue (with optional fused row/col abs-max) ----
    float rowm[2][2] = {{0.f, 0.f}, {0.f, 0.f}};
    float colm[8][2];
    if (EPI & 8) {
#pragma unroll
        for (int nt = 0; nt < 8; nt++) { colm[nt][0] = 0.f; colm[nt][1] = 0.f; }
    }
#pragma unroll
    for (int mt = 0; mt < 2; mt++)
#pragma unroll
        for (int nt = 0; nt < 8; nt++) {
            const int rbase = m0 + wm0 + mt * 16 + (lane >> 2);
            const int cn = n0 + nt * 8 + (lane & 3) * 2;
            const float sb0 = sbv[cn], sb1 = sbv[cn + 1];
#pragma unroll
            for (int h2 = 0; h2 < 2; h2++) {
                const int m = rbase + h2 * 8;
                const float sam = sa[m];
                float v0 = ((float)acc_hh[mt][nt][h2 * 2] +
                            (float)acc_x[mt][nt][h2 * 2] * (1.0f / 256.0f)) * sam * sb0;
                float v1 = ((float)acc_hh[mt][nt][h2 * 2 + 1] +
                            (float)acc_x[mt][nt][h2 * 2 + 1] * (1.0f / 256.0f)) * sam * sb1;
                const size_t ob = (size_t)m * out_stride + cn;
                const int base = EPI & 3;
                if (base == 0) {
                    if (bias != nullptr) { v0 += bias[cn]; v1 += bias[cn + 1]; }
                } else if (base == 1) {
                    v0 += bias[cn] + addsrc[ob];
                    v1 += bias[cn + 1] + addsrc[ob + 1];
                } else {
                    v0 = fmaxf(v0 + bias[cn], 0.f);
                    v1 = fmaxf(v1 + bias[cn + 1], 0.f);
                }
                *(float2*)(outf + ob) = make_float2(v0, v1);
                if (EPI & 4)
                    rowm[mt][h2] = fmaxf(rowm[mt][h2], fmaxf(fabsf(v0), fabsf(v1)));
                if (EPI & 8) {
                    colm[nt][0] = fmaxf(colm[nt][0], fabsf(v0));
                    colm[nt][1] = fmaxf(colm[nt][1], fabsf(v1));
                }
            }
        }
    if (EPI & 4) {
#pragma unroll
        for (int mt = 0; mt < 2; mt++)
#pragma unroll
            for (int h2 = 0; h2 < 2; h2++) {
                const int m = m0 + wm0 + mt * 16 + (lane >> 2) + h2 * 8;
                atomicMax(rmrow + m, __float_as_uint(rowm[mt][h2]));
            }
    }
    if (EPI & 8) {
#pragma unroll
        for (int nt = 0; nt < 8; nt++) {
            const int cn = n0 + nt * 8 + (lane & 3) * 2;
            atomicMax(rmcol + cn, __float_as_uint(colm[nt][0]));
            atomicMax(rmcol + cn + 1, __float_as_uint(colm[nt][1]));
        }
    }
}

// ===================== quantization =======================================
__device__ __forceinline__ void tl_qpair(float y, int8_t& o1, int8_t& o2) {
    const float i1 = rintf(y);
    float i2 = rintf((y - i1) * 256.f);
    i2 = fminf(fmaxf(i2, -127.f), 127.f);
    o1 = (int8_t)(int)i1;
    o2 = (int8_t)(int)i2;
}

// Parallel column abs-max: grid (C/32, R/256), block (32,8); atomicMax on f32 bits.
__global__ void tl_colmax2(const float* __restrict__ in, int C,
                           unsigned* __restrict__ rawmax) {
    const int tx = threadIdx.x, ty = threadIdx.y;
    const int c = blockIdx.x * 32 + tx;
    const int r0 = blockIdx.y * 256;
    __shared__ float red[8][33];
    float m = 0.f;
    for (int r = r0 + ty; r < r0 + 256; r += 8)
        m = fmaxf(m, fabsf(in[(size_t)r * C + c]));
    red[ty][tx] = m;
    __syncthreads();
    if (ty == 0) {
        float M = red[0][tx];
#pragma unroll
        for (int i = 1; i < 8; i++) M = fmaxf(M, red[i][tx]);
        atomicMax(rawmax + c, __float_as_uint(M));
    }
}

// Transpose-quantize [R][C] f32 -> d1,d2 [C][R] using rawmax; writes scale[c]=max/127.
__global__ void tl_tq(const float* __restrict__ in, const unsigned* __restrict__ rawmax,
                      int R, int C, int8_t* __restrict__ d1, int8_t* __restrict__ d2,
                      float* __restrict__ scale) {
    __shared__ float t[32][33];
    const int c0 = blockIdx.x * 32, r0 = blockIdx.y * 32;
    const int tx = threadIdx.x, ty = threadIdx.y;
#pragma unroll
    for (int i = 0; i < 32; i += 8)
        t[ty + i][tx] = in[(size_t)(r0 + ty + i) * C + c0 + tx];
    if (blockIdx.y == 0 && ty == 0)
        scale[c0 + tx] = __uint_as_float(rawmax[c0 + tx]) * (1.0f / 127.0f);
    __syncthreads();
#pragma unroll
    for (int cc = ty; cc < 32; cc += 8) {
        const float M = __uint_as_float(rawmax[c0 + cc]);
        const float inv = (M > 0.f) ? 127.f / M : 0.f;
        const size_t o = (size_t)(c0 + cc) * R + r0 + tx;
        tl_qpair(t[tx][cc] * inv, d1[o], d2[o]);
    }
}

// Column quantize (two-pass within one block; used for weights inside prepQ).
__device__ void tl_wquant_body(const float* __restrict__ in, int R, int C,
                               int8_t* __restrict__ d1, int8_t* __restrict__ d2,
                               float* __restrict__ scale, int bx) {
    const int tx = threadIdx.x, ty = threadIdx.y;
    const int c0 = bx * 32;
    __shared__ float red[8][33];
    __shared__ float invs[32];
    __shared__ float t[32][33];
    float m = 0.f;
    for (int r = ty; r < R; r += 8)
        m = fmaxf(m, fabsf(in[(size_t)r * C + c0 + tx]));
    red[ty][tx] = m;
    __syncthreads();
    if (ty == 0) {
        float M = red[0][tx];
#pragma unroll
        for (int i = 1; i < 8; i++) M = fmaxf(M, red[i][tx]);
        invs[tx] = (M > 0.f) ? 127.f / M : 0.f;
        scale[c0 + tx] = M * (1.0f / 127.0f);
    }
    __syncthreads();
    for (int r0 = 0; r0 < R; r0 += 32) {
        for (int i = ty; i < 32; i += 8)
            t[i][tx] = in[(size_t)(r0 + i) * C + c0 + tx];
        __syncthreads();
#pragma unroll
        for (int cc = ty; cc < 32; cc += 8) {
            const float v = t[tx][cc] * invs[cc];
            const size_t o = (size_t)(c0 + cc) * R + r0 + tx;
            tl_qpair(v, d1[o], d2[o]);
        }
        __syncthreads();
    }
}

// Warp-per-row quantize (own max; float4 vectorized) — used for x in prepQ.
__device__ void tl_rowquant_warp(const float* __restrict__ in, int ncols,
                                 int8_t* __restrict__ d1, int8_t* __restrict__ d2,
                                 float* __restrict__ scale, int row) {
    const int tx = threadIdx.x;
    const float* r = in + (size_t)row * ncols;
    float m = 0.f;
    for (int j = tx * 4; j < ncols; j += 128) {
        const float4 v = *(const float4*)(r + j);
        m = fmaxf(m, fmaxf(fmaxf(fabsf(v.x), fabsf(v.y)), fmaxf(fabsf(v.z), fabsf(v.w))));
    }
#pragma unroll
    for (int o = 16; o; o >>= 1) m = fmaxf(m, __shfl_xor_sync(0xffffffffu, m, o));
    const float inv = (m > 0.f) ? 127.f / m : 0.f;
    if (tx == 0) scale[row] = m * (1.0f / 127.0f);
    for (int j = tx * 4; j < ncols; j += 128) {
        const float4 v = *(const float4*)(r + j);
        int8_t a1, a2, b1, b2, c1, c2, e1, e2;
        tl_qpair(v.x * inv, a1, a2);
        tl_qpair(v.y * inv, b1, b2);
        tl_qpair(v.z * inv, c1, c2);
        tl_qpair(v.w * inv, e1, e2);
        const uint32_t p1 = (uint32_t)(uint8_t)a1 | ((uint32_t)(uint8_t)b1 << 8) |
                            ((uint32_t)(uint8_t)c1 << 16) | ((uint32_t)(uint8_t)e1 << 24);
        const uint32_t p2 = (uint32_t)(uint8_t)a2 | ((uint32_t)(uint8_t)b2 << 8) |
                            ((uint32_t)(uint8_t)c2 << 16) | ((uint32_t)(uint8_t)e2 << 24);
        const size_t o = (size_t)row * ncols + j;
        *(uint32_t*)(d1 + o) = p1;
        *(uint32_t*)(d2 + o) = p2;
    }
}

// Row quantize with PRECOMPUTED row max (from fused GEMM epilogue) — single read.
__global__ void tl_rowquant2(const float* __restrict__ in, int ncols,
                             const unsigned* __restrict__ rmax,
                             int8_t* __restrict__ d1, int8_t* __restrict__ d2,
                             float* __restrict__ scale) {
    const int row = blockIdx.x * 8 + (int)threadIdx.y;
    const int tx = threadIdx.x;
    const float M = __uint_as_float(rmax[row]);
    const float inv = (M > 0.f) ? 127.f / M : 0.f;
    if (tx == 0) scale[row] = M * (1.0f / 127.0f);
    const float* r = in + (size_t)row * ncols;
    for (int j = tx * 4; j < ncols; j += 128) {
        const float4 v = *(const float4*)(r + j);
        int8_t a1, a2, b1, b2, c1, c2, e1, e2;
        tl_qpair(v.x * inv, a1, a2);
        tl_qpair(v.y * inv, b1, b2);
        tl_qpair(v.z * inv, c1, c2);
        tl_qpair(v.w * inv, e1, e2);
        const uint32_t p1 = (uint32_t)(uint8_t)a1 | ((uint32_t)(uint8_t)b1 << 8) |
                            ((uint32_t)(uint8_t)c1 << 16) | ((uint32_t)(uint8_t)e1 << 24);
        const uint32_t p2 = (uint32_t)(uint8_t)a2 | ((uint32_t)(uint8_t)b2 << 8) |
                            ((uint32_t)(uint8_t)c2 << 16) | ((uint32_t)(uint8_t)e2 << 24);
        const size_t o = (size_t)row * ncols + j;
        *(uint32_t*)(d1 + o) = p1;
        *(uint32_t*)(d2 + o) = p2;
    }
}

// Launch #0: Wq/Wk/Wv quant (blocks 0..191) + x rowquant (192..703) + rawmax zero (704).
__global__ void tl_prepQ(const float* __restrict__ Wq, int8_t* wq1, int8_t* wq2, float* swq,
                         const float* __restrict__ Wk, int8_t* wk1, int8_t* wk2, float* swk,
                         const float* __restrict__ Wv, int8_t* wv1, int8_t* wv2, float* swv,
                         const float* __restrict__ x, int8_t* xd1, int8_t* xd2, float* sx,
                         unsigned* rmbase, int rmcount) {
    const int b = blockIdx.x;
    if (b < 64) {
        tl_wquant_body(Wq, D, H, wq1, wq2, swq, b);
    } else if (b < 128) {
        tl_wquant_body(Wk, D, H, wk1, wk2, swk, b - 64);
    } else if (b < 192) {
        tl_wquant_body(Wv, D, H, wv1, wv2, swv, b - 128);
    } else if (b < 704) {
        tl_rowquant_warp(x, D, xd1, xd2, sx, (b - 192) * 8 + (int)threadIdx.y);
    } else {
        const int t = (int)threadIdx.y * 32 + (int)threadIdx.x;
        for (int i = t; i < rmcount; i += 256) rmbase[i] = 0u;
    }
}

// Row-wise causal softmax; writes fp32 attn (zeros above diag) + int8 digits.
__global__ void tl_softmax(const float* __restrict__ scores, float* __restrict__ attn,
                           int8_t* __restrict__ ad1, int8_t* __restrict__ ad2,
                           float* __restrict__ sat) {
    const int row = blockIdx.x;
    const int tid = threadIdx.x;  // 256
    const int nvalid = row + 1;
    const float scale = 0.02209708691207961f;  // 1/sqrt(2048)
    const float* srow = scores + (size_t)row * S;
    __shared__ float red[8];

    float v[16];
    float mx = -1e30f;
#pragma unroll
    for (int t = 0; t < 16; t++) {
        const int j = tid + t * 256;
        const float x = (j < nvalid) ? srow[j] * scale : -1e30f;
        v[t] = x;
        mx = fmaxf(mx, x);
    }
#pragma unroll
    for (int o = 16; o; o >>= 1) mx = fmaxf(mx, __shfl_xor_sync(0xffffffffu, mx, o));
    if ((tid & 31) == 0) red[tid >> 5] = mx;
    __syncthreads();
    float rmax = red[0];
#pragma unroll
    for (int i = 1; i < 8; i++) rmax = fmaxf(rmax, red[i]);
    __syncthreads();

    float sum = 0.f;
#pragma unroll
    for (int t = 0; t < 16; t++) {
        const int j = tid + t * 256;
        const float e = (j < nvalid) ? __expf(v[t] - rmax) : 0.f;
        v[t] = e;
        sum += e;
    }
#pragma unroll
    for (int o = 16; o; o >>= 1) sum += __shfl_xor_sync(0xffffffffu, sum, o);
    if ((tid & 31) == 0) red[tid >> 5] = sum;
    __syncthreads();
    float tot = 0.f;
#pragma unroll
    for (int i = 0; i < 8; i++) tot += red[i];
    const float inv = 1.f / tot;
    if (tid == 0) sat[row] = inv * (1.0f / 127.0f);

#pragma unroll
    for (int t = 0; t < 16; t++) {
        const int j = tid + t * 256;
        const size_t o = (size_t)row * S + j;
        attn[o] = v[t] * inv;
        tl_qpair(v[t] * 127.f, ad1[o], ad2[o]);
    }
}

// ===================== host launch =========================================
extern "C" void kernel_launch(void* const* d_in, const int* in_sizes, int n_in,
                              void* d_out, int out_size) {
    const float* x  = (const float*)d_in[0];
    const float* Wq = (const float*)d_in[1];
    const float* bq = (const float*)d_in[2];
    const float* Wk = (const float*)d_in[3];
    const float* bk = (const float*)d_in[4];
    const float* Wv = (const float*)d_in[5];
    const float* bv = (const float*)d_in[6];
    const float* Wo = (const float*)d_in[7];
    const float* bo = (const float*)d_in[8];
    const float* W1 = (const float*)d_in[9];
    const float* b1 = (const float*)d_in[10];
    const float* W2 = (const float*)d_in[11];
    const float* b2 = (const float*)d_in[12];
    float* out  = (float*)d_out;        // [S,D]
    float* attn = out + NSD;            // [S,S]

    TlScratch* s = nullptr;
    cudaGetSymbolAddress((void**)&s, g_s);

    cudaFuncSetAttribute(tl_gemm_i8<0>, cudaFuncAttributeMaxDynamicSharedMemorySize, TL_SMEM_TOTAL);
    cudaFuncSetAttribute(tl_gemm_i8<1>, cudaFuncAttributeMaxDynamicSharedMemorySize, TL_SMEM_TOTAL);
    cudaFuncSetAttribute(tl_gemm_i8<4>, cudaFuncAttributeMaxDynamicSharedMemorySize, TL_SMEM_TOTAL);
    cudaFuncSetAttribute(tl_gemm_i8<5>, cudaFuncAttributeMaxDynamicSharedMemorySize, TL_SMEM_TOTAL);
    cudaFuncSetAttribute(tl_gemm_i8<6>, cudaFuncAttributeMaxDynamicSharedMemorySize, TL_SMEM_TOTAL);
    cudaFuncSetAttribute(tl_gemm_i8<8>, cudaFuncAttributeMaxDynamicSharedMemorySize, TL_SMEM_TOTAL);

    // Side streams + events for aux/GEMM overlap. Created on first call
    // (outside graph capture), reused on the captured call. Fork/join via
    // events is the supported stream-capture pattern.
    static cudaStream_t s2 = nullptr, s3 = nullptr;
    static cudaEvent_t eP = nullptr, eV = nullptr, eVT = nullptr, eW = nullptr;
    if (s2 == nullptr) {
        cudaStreamCreateWithFlags(&s2, cudaStreamNonBlocking);
        cudaStreamCreateWithFlags(&s3, cudaStreamNonBlocking);
        cudaEventCreateWithFlags(&eP, cudaEventDisableTiming);
        cudaEventCreateWithFlags(&eV, cudaEventDisableTiming);
        cudaEventCreateWithFlags(&eVT, cudaEventDisableTiming);
        cudaEventCreateWithFlags(&eW, cudaEventDisableTiming);
    }

    const dim3 qb(32, 8);
    const dim3 g_sh(H / 64, S / 128);    // [S,H]
    const dim3 g_ss(S / 64, S / 128);    // [S,S]
    const dim3 g_sd(D / 64, S / 128);    // [S,D]

    // rawmax block: rmvt,rm1 (H) + rmo,rm2 (D) + rmq,rmkf,rmao,rmres,rmh (S each)
    const int rmcount = 2 * H + 2 * D + 5 * S;

    // main stream: prep -> Q/K/V GEMMs
    tl_prepQ<<<705, qb>>>(Wq, s->wq1, s->wq2, s->swq,
                          Wk, s->wk1, s->wk2, s->swk,
                          Wv, s->wv1, s->wv2, s->swv,
                          x, s->xd1, s->xd2, s->sx, s->rmvt, rmcount);
    cudaEventRecord(eP, 0);
    tl_gemm_i8<4><<<g_sh, 128, TL_SMEM_TOTAL>>>(s->xd1, s->xd2, s->sx, D,
        s->wq1, s->wq2, s->swq, D, D, 0, s->qf, bq, nullptr, H, s->rmq, nullptr);
    tl_gemm_i8<4><<<g_sh, 128, TL_SMEM_TOTAL>>>(s->xd1, s->xd2, s->sx, D,
        s->wk1, s->wk2, s->swk, D, D, 0, s->kf, bk, nullptr, H, s->rmkf, nullptr);
    tl_gemm_i8<8><<<g_sh, 128, TL_SMEM_TOTAL>>>(s->xd1, s->xd2, s->sx, D,
        s->wv1, s->wv2, s->swv, D, D, 0, s->vf, bv, nullptr, H, nullptr, s->rmvt);
    cudaEventRecord(eV, 0);

    // s2 (after prep): Wo/W1/W2 quant, overlapped with the GEMM chain
    cudaStreamWaitEvent(s2, eP, 0);
    tl_colmax2<<<dim3(D / 32, H / 256), qb, 0, s2>>>(Wo, D, s->rmo);
    tl_tq<<<dim3(D / 32, H / 32), qb, 0, s2>>>(Wo, s->rmo, H, D, s->wo1, s->wo2, s->swo);
    tl_colmax2<<<dim3(H / 32, D / 256), qb, 0, s2>>>(W1, H, s->rm1);
    tl_tq<<<dim3(H / 32, D / 32), qb, 0, s2>>>(W1, s->rm1, D, H, s->w11, s->w12, s->sw1);
    tl_colmax2<<<dim3(D / 32, H / 256), qb, 0, s2>>>(W2, D, s->rm2);
    tl_tq<<<dim3(D / 32, H / 32), qb, 0, s2>>>(W2, s->rm2, H, D, s->w21, s->w22, s->sw2);
    cudaEventRecord(eW, s2);

    // s3 (after V GEMM): vf transpose-quantize, overlapped with scores+softmax
    cudaStreamWaitEvent(s3, eV, 0);
    tl_tq<<<dim3(H / 32, S / 32), qb, 0, s3>>>(s->vf, s->rmvt, S, H, s->vt1, s->vt2, s->svt);
    cudaEventRecord(eVT, s3);

    // main: q/k quant -> scores -> softmax
    tl_rowquant2<<<S / 8, qb>>>(s->qf, H, s->rmq, s->qd1, s->qd2, s->sq);
    tl_rowquant2<<<S / 8, qb>>>(s->kf, H, s->rmkf, s->kd1, s->kd2, s->sk);
    tl_gemm_i8<0><<<g_ss, 128, TL_SMEM_TOTAL>>>(s->qd1, s->qd2, s->sq, H,
        s->kd1, s->kd2, s->sk, H, H, 1, s->scores, nullptr, nullptr, S, nullptr, nullptr);
    tl_softmax<<<S, 256>>>(s->scores, attn, s->at1, s->at2, s->sat);

    // join s3, then attn_out = attn @ v (K clamped)
    cudaStreamWaitEvent(0, eVT, 0);
    tl_gemm_i8<4><<<g_sh, 128, TL_SMEM_TOTAL>>>(s->at1, s->at2, s->sat, S,
        s->vt1, s->vt2, s->svt, S, S, 2, s->aof, nullptr, nullptr, H, s->rmao, nullptr);
    tl_rowquant2<<<S / 8, qb>>>(s->aof, H, s->rmao, s->ao1, s->ao2, s->sao);

    // join s2, then resid = x + ao@Wo + bo
    cudaStreamWaitEvent(0, eW, 0);
    tl_gemm_i8<5><<<g_sd, 128, TL_SMEM_TOTAL>>>(s->ao1, s->ao2, s->sao, H,
        s->wo1, s->wo2, s->swo, H, H, 0, s->residf, bo, x, D, s->rmres, nullptr);
    tl_rowquant2<<<S / 8, qb>>>(s->residf, D, s->rmres, s->rd1, s->rd2, s->sr);
    // h = relu(resid@W1 + b1)
    tl_gemm_i8<6><<<g_sh, 128, TL_SMEM_TOTAL>>>(s->rd1, s->rd2, s->sr, D,
        s->w11, s->w12, s->sw1, D, D, 0, s->hf, b1, nullptr, H, s->rmh, nullptr);
    tl_rowquant2<<<S / 8, qb>>>(s->hf, H, s->rmh, s->hd1, s->hd2, s->sh);
    // out = resid + h@W2 + b2
    tl_gemm_i8<1><<<g_sd, 128, TL_SMEM_TOTAL>>>(s->hd1, s->hd2, s->sh, H,
        s->w21, s->w22, s->sw2, H, H, 0, out, b2, s->residf, D, nullptr, nullptr);
}